// round 3
// baseline (speedup 1.0000x reference)
#include <cuda_runtime.h>
#include <math.h>

typedef unsigned long long u64;

#define T_   1000
#define B_   16
#define I_   440
#define H_   1024
#define P_   512
#define R_   4096   // 4*H, column-interleaved: col = hh*4 + gate (f,i,o,c)
#define NBLK 128

// ---------------- device scratch (no runtime allocation allowed) ----------------
static __device__ float g_G[(size_t)T_ * B_ * R_];  // 262 MB: input projections [t][b][col]
static __device__ float g_MT[(size_t)H_ * R_];      // 16 MB: fused recurrent weights [k][col]
static __device__ float g_h[2][H_ * B_];            // double-buffered hidden [buf][k][b]
static __device__ unsigned g_count = 0;             // barrier arrivals (self-resetting)
static __device__ unsigned g_gen   = 0;             // barrier generation

// ---------------- f32x2 packed-pair helpers (FFMA2 path on sm_103a) ----------------
__device__ __forceinline__ u64 pack2(float lo, float hi) {
    u64 r; asm("mov.b64 %0, {%1, %2};" : "=l"(r) : "f"(lo), "f"(hi)); return r;
}
__device__ __forceinline__ void unpack2(u64 v, float& lo, float& hi) {
    asm("mov.b64 {%0, %1}, %2;" : "=f"(lo), "=f"(hi) : "l"(v));
}
__device__ __forceinline__ u64 ffma2(u64 a, u64 b, u64 c) {
    u64 d; asm("fma.rn.f32x2 %0, %1, %2, %3;" : "=l"(d) : "l"(a), "l"(b), "l"(c)); return d;
}
__device__ __forceinline__ u64 fadd2(u64 a, u64 b) {
    u64 d; asm("add.rn.f32x2 %0, %1, %2;" : "=l"(d) : "l"(a), "l"(b)); return d;
}

// ---------------- grid-wide barrier (graph-replay safe, 128 blocks) ----------------
__device__ __forceinline__ void gsync() {
    __threadfence();
    __syncthreads();
    if (threadIdx.x == 0) {
        volatile unsigned* vgen = (volatile unsigned*)&g_gen;
        unsigned gen = *vgen;
        if (atomicAdd(&g_count, 1u) == NBLK - 1) {
            g_count = 0;
            __threadfence();
            *vgen = gen + 1;
        } else {
            while (*vgen == gen) { }
        }
        __threadfence();
    }
    __syncthreads();
}

// =====================================================================
// Kernel 1: G[m][col] = sum_k X[m][k] * W_gate(col)[hh(col)][k] + bias
//   m = t*16+b (16000), col = hh*4+gate (4096, interleaved), k = I (440)
//   128x128 tile, BK=8, 256 threads, per-thread 8m x 8n via 32 fma.f32x2.
//   A staged duplicated ({a,a}) in smem so the inner loop has zero packs.
// =====================================================================
__global__ __launch_bounds__(256) void gemm_input(
    const float* __restrict__ X,
    const float* __restrict__ wf, const float* __restrict__ wi,
    const float* __restrict__ wo, const float* __restrict__ wc,
    const float* __restrict__ bf, const float* __restrict__ bi,
    const float* __restrict__ bo, const float* __restrict__ bc)
{
    __shared__ __align__(16) u64   As[8][128];   // duplicated pairs {a,a}, 8 KB
    __shared__ __align__(16) float Bs[8][128];   // 4 KB

    const int tid = threadIdx.x;
    const int n0  = blockIdx.x * 128;       // interleaved col base (hh base = n0>>2)
    const int m0  = blockIdx.y * 128;

    const int lr = tid >> 1;                // 0..127
    const int lc = (tid & 1) * 4;           // 0 or 4

    const float* wsel[4] = {wf, wi, wo, wc};
    const int bgate = lr & 3;
    const int bhh   = (n0 >> 2) + (lr >> 2);
    const float* aptr = X + (size_t)(m0 + lr) * I_ + lc;
    const float* bptr = wsel[bgate] + (size_t)bhh * I_ + lc;

    float4 areg = *(const float4*)aptr;
    float4 breg = *(const float4*)bptr;

    const int tm = (tid >> 4) * 8;
    const int tn = (tid & 15) * 8;

    u64 acc[8][4];
#pragma unroll
    for (int i = 0; i < 8; ++i)
#pragma unroll
        for (int j = 0; j < 4; ++j) acc[i][j] = 0ull;

    for (int k0 = 0; k0 < I_; k0 += 8) {
        As[lc + 0][lr] = pack2(areg.x, areg.x);
        As[lc + 1][lr] = pack2(areg.y, areg.y);
        As[lc + 2][lr] = pack2(areg.z, areg.z);
        As[lc + 3][lr] = pack2(areg.w, areg.w);
        Bs[lc + 0][lr] = breg.x; Bs[lc + 1][lr] = breg.y;
        Bs[lc + 2][lr] = breg.z; Bs[lc + 3][lr] = breg.w;
        __syncthreads();
        if (k0 + 8 < I_) {
            areg = *(const float4*)(aptr + k0 + 8);
            breg = *(const float4*)(bptr + k0 + 8);
        }
#pragma unroll
        for (int kk = 0; kk < 8; ++kk) {
            u64 a[8], b2[4];
            *(float4*)&a[0] = *(const float4*)&As[kk][tm];
            *(float4*)&a[2] = *(const float4*)&As[kk][tm + 2];
            *(float4*)&a[4] = *(const float4*)&As[kk][tm + 4];
            *(float4*)&a[6] = *(const float4*)&As[kk][tm + 6];
            *(float4*)&b2[0] = *(const float4*)&Bs[kk][tn];
            *(float4*)&b2[2] = *(const float4*)&Bs[kk][tn + 4];
#pragma unroll
            for (int i = 0; i < 8; ++i)
#pragma unroll
                for (int j = 0; j < 4; ++j)
                    acc[i][j] = ffma2(a[i], b2[j], acc[i][j]);
        }
        __syncthreads();
    }

    // bias per column (interleaved): gate = (tn+j)&3, hh = (n0>>2)+((tn+j)>>2)
    const float* bsel[4] = {bf, bi, bo, bc};
    float bv[8];
#pragma unroll
    for (int j = 0; j < 8; ++j)
        bv[j] = bsel[(tn + j) & 3][(n0 >> 2) + ((tn + j) >> 2)];

#pragma unroll
    for (int i = 0; i < 8; ++i) {
        float cv[8];
#pragma unroll
        for (int jp = 0; jp < 4; ++jp) unpack2(acc[i][jp], cv[2 * jp], cv[2 * jp + 1]);
        float* crow = g_G + (size_t)(m0 + tm + i) * R_ + n0 + tn;
        float4 v0, v1;
        v0.x = cv[0] + bv[0]; v0.y = cv[1] + bv[1]; v0.z = cv[2] + bv[2]; v0.w = cv[3] + bv[3];
        v1.x = cv[4] + bv[4]; v1.y = cv[5] + bv[5]; v1.z = cv[6] + bv[6]; v1.w = cv[7] + bv[7];
        *(float4*)(crow)     = v0;
        *(float4*)(crow + 4) = v1;
    }
}

// =====================================================================
// Kernel 2: MT[h][col] = sum_p wym[p][h] * Wr_gate(col)[hh(col)][p]
//   Folds output projection into the recurrence. m=h (1024), col (4096), k=p (512)
// =====================================================================
__global__ __launch_bounds__(256) void gemm_comb(
    const float* __restrict__ wym,
    const float* __restrict__ tf, const float* __restrict__ ti,
    const float* __restrict__ to_, const float* __restrict__ tc)
{
    __shared__ __align__(16) float As[8][128];
    __shared__ __align__(16) float Bs[8][128];

    const int tid = threadIdx.x;
    const int n0  = blockIdx.x * 128;
    const int m0  = blockIdx.y * 128;

    const int akk = tid >> 5;
    const int amm = (tid & 31) * 4;
    const float* aptr = wym + (size_t)akk * H_ + m0 + amm;

    const float* wsel[4] = {tf, ti, to_, tc};
    const int lr = tid >> 1;
    const int lc = (tid & 1) * 4;
    const float* bptr = wsel[lr & 3] + (size_t)((n0 >> 2) + (lr >> 2)) * P_ + lc;

    float4 areg = *(const float4*)aptr;
    float4 breg = *(const float4*)bptr;

    const int tm = (tid >> 4) * 8;
    const int tn = (tid & 15) * 8;

    float acc[8][8];
#pragma unroll
    for (int i = 0; i < 8; ++i)
#pragma unroll
        for (int j = 0; j < 8; ++j) acc[i][j] = 0.f;

    for (int k0 = 0; k0 < P_; k0 += 8) {
        *(float4*)&As[akk][amm] = areg;
        Bs[lc + 0][lr] = breg.x; Bs[lc + 1][lr] = breg.y;
        Bs[lc + 2][lr] = breg.z; Bs[lc + 3][lr] = breg.w;
        __syncthreads();
        if (k0 + 8 < P_) {
            areg = *(const float4*)(aptr + (size_t)(k0 + 8) * H_);
            breg = *(const float4*)(bptr + k0 + 8);
        }
#pragma unroll
        for (int kk = 0; kk < 8; ++kk) {
            float a[8], b[8];
            *(float4*)(a)     = *(const float4*)&As[kk][tm];
            *(float4*)(a + 4) = *(const float4*)&As[kk][tm + 4];
            *(float4*)(b)     = *(const float4*)&Bs[kk][tn];
            *(float4*)(b + 4) = *(const float4*)&Bs[kk][tn + 4];
#pragma unroll
            for (int i = 0; i < 8; ++i)
#pragma unroll
                for (int j = 0; j < 8; ++j)
                    acc[i][j] = fmaf(a[i], b[j], acc[i][j]);
        }
        __syncthreads();
    }

#pragma unroll
    for (int i = 0; i < 8; ++i) {
        float* crow = g_MT + (size_t)(m0 + tm + i) * R_ + n0 + tn;
        *(float4*)(crow)     = make_float4(acc[i][0], acc[i][1], acc[i][2], acc[i][3]);
        *(float4*)(crow + 4) = make_float4(acc[i][4], acc[i][5], acc[i][6], acc[i][7]);
    }
}

// =====================================================================
// Kernel 3: persistent recurrence. 128 blocks x 256 threads, ONE gsync/step.
//   Block owns 8 hh-cells (32 interleaved cols) x all 16 b.
//   Warps split K=1024 (128 each), reduce partials in SMEM, block does its
//   own pointwise. h double-buffered in global (read via .cg: L1-incoherent).
//   MT slice (128 KB/block) stays L1-resident across all 1000 steps.
// =====================================================================
__device__ __forceinline__ float sigmoidf_(float x) { return 1.f / (1.f + __expf(-x)); }

// smem layout (dynamic, 86272 B):
//  [0,      65536)  h_s  : float [1024][16]
//  [65536,  83968)  part : u64   [8][32][9]  (bp dim padded 8->9)
//  [83968,  86272)  gsm  : float [16][36]    (row padded 32->36)
#define SM_PART 65536
#define SM_GSM  83968
#define SM_TOT  86272

__global__ __launch_bounds__(256, 1) void lstm_rec(float* __restrict__ out)
{
    extern __shared__ __align__(16) char smem[];
    float* h_s  = (float*)smem;
    u64*   part = (u64*)(smem + SM_PART);
    float* gsm  = (float*)(smem + SM_GSM);

    const int tid  = threadIdx.x;
    const int bid  = blockIdx.x;
    const int wid  = tid >> 5;
    const int lane = tid & 31;

    // zero both h buffers
    {
        int i = bid * 256 + tid;             // exactly covers 2*1024*16
        ((float*)g_h)[i] = 0.f;
    }
    gsync();

    const int hh0 = bid * 8;                 // this block's hh cells
    const int c0  = bid * 32;                // interleaved col base = hh0*4
    const int rg  = lane >> 2;               // 0..7  (4 cols each)
    const int bg  = lane & 3;                // 0..3  (4 b each)
    const int b0  = bg * 4;

    const int pb  = tid >> 3;                // pointwise: b
    const int phl = tid & 7;                 //            hh local
    float cstate = 0.f;                      // cell state (tid<128 own one cell)

    const float* MTbase = g_MT + (size_t)(wid * 128) * R_ + c0 + rg * 4;

    for (int t = 0; t < T_; ++t) {
        // ---- each warp stages its own K-chunk of h (L1-bypassing loads) ----
        // warp chunk = 128 k x 16 b = 2048 floats = 512 float4 = 16 iters x 32 lanes
        {
            const float4* src = (const float4*)(&g_h[t & 1][wid * 128 * 16]);
            float4* dst = (float4*)(&h_s[wid * 128 * 16]);
#pragma unroll
            for (int i = 0; i < 16; ++i) {
                int idx = i * 32 + lane;
                dst[idx] = __ldcg(src + idx);
            }
            __syncwarp();
        }

        // ---- matmul over this warp's K-chunk: 4 cols x 16 b per lane ----
        u64 acc[4][2];
#pragma unroll
        for (int i = 0; i < 4; ++i) { acc[i][0] = 0ull; acc[i][1] = 0ull; }

        const float* mp = MTbase;
        const float* hp = &h_s[wid * 128 * 16 + b0];
#pragma unroll 4
        for (int kk = 0; kk < 128; ++kk) {
            float4 m = *(const float4*)mp;
            mp += R_;
            u64 hv[2];
            *(float4*)hv = *(const float4*)hp;
            hp += 16;
            u64 mm;
            mm = pack2(m.x, m.x);
            acc[0][0] = ffma2(mm, hv[0], acc[0][0]); acc[0][1] = ffma2(mm, hv[1], acc[0][1]);
            mm = pack2(m.y, m.y);
            acc[1][0] = ffma2(mm, hv[0], acc[1][0]); acc[1][1] = ffma2(mm, hv[1], acc[1][1]);
            mm = pack2(m.z, m.z);
            acc[2][0] = ffma2(mm, hv[0], acc[2][0]); acc[2][1] = ffma2(mm, hv[1], acc[2][1]);
            mm = pack2(m.w, m.w);
            acc[3][0] = ffma2(mm, hv[0], acc[3][0]); acc[3][1] = ffma2(mm, hv[1], acc[3][1]);
        }

        // ---- warp partials -> smem ----
#pragma unroll
        for (int i = 0; i < 4; ++i) {
#pragma unroll
            for (int j = 0; j < 2; ++j)
                part[(size_t)(wid * 32 + rg * 4 + i) * 9 + bg * 2 + j] = acc[i][j];
        }
        __syncthreads();

        // ---- reduce 8 warp partials; scatter to gsm[b][ci] ----
        {
            const int ri = tid >> 3;        // column index within block (0..31)
            const int bp = tid & 7;         // b-pair index (b = 2bp, 2bp+1)
            u64 s = part[(size_t)ri * 9 + bp];
#pragma unroll
            for (int w = 1; w < 8; ++w)
                s = fadd2(s, part[(size_t)(w * 32 + ri) * 9 + bp]);
            float lo, hi;
            unpack2(s, lo, hi);
            gsm[(2 * bp) * 36 + ri]     = lo;
            gsm[(2 * bp + 1) * 36 + ri] = hi;
        }
        __syncthreads();

        // ---- pointwise LSTM update for owned cells ----
        if (tid < 128) {
            float4 gd = *(const float4*)&gsm[pb * 36 + phl * 4];
            const float4* Gt = (const float4*)(g_G + ((size_t)(t * B_ + pb) << 12)
                                               + (size_t)(hh0 + phl) * 4);
            float4 gg = __ldcs(Gt);
            float zf = gg.x + gd.x;
            float zi = gg.y + gd.y;
            float zo = gg.z + gd.z;
            float zc = gg.w + gd.w;
            float ft = sigmoidf_(zf);
            float it = sigmoidf_(zi);
            float ot = sigmoidf_(zo);
            cstate = it * tanhf(zc) + ft * cstate;
            float h = ot * tanhf(cstate);
            g_h[(t + 1) & 1][(hh0 + phl) * 16 + pb] = h;
            out[((size_t)(t * B_ + pb) << 10) + hh0 + phl] = h;
        }

        gsync();   // all h writes visible before anyone stages next step
    }
}

// =====================================================================
// launch
// =====================================================================
extern "C" void kernel_launch(void* const* d_in, const int* in_sizes, int n_in,
                              void* d_out, int out_size)
{
    const float* x     = (const float*)d_in[0];
    const float* wfx_w = (const float*)d_in[1];
    const float* wfx_b = (const float*)d_in[2];
    const float* wix_w = (const float*)d_in[3];
    const float* wix_b = (const float*)d_in[4];
    const float* wox_w = (const float*)d_in[5];
    const float* wox_b = (const float*)d_in[6];
    const float* wcx_w = (const float*)d_in[7];
    const float* wcx_b = (const float*)d_in[8];
    const float* tfy_w = (const float*)d_in[9];
    const float* tiy_w = (const float*)d_in[10];
    const float* toy_w = (const float*)d_in[11];
    const float* tcy_w = (const float*)d_in[12];
    const float* wym_w = (const float*)d_in[13];
    float* out = (float*)d_out;

    // G = x @ Wx^T + b, interleaved columns (all timesteps)
    gemm_input<<<dim3(R_ / 128, 16000 / 128), 256>>>(
        x, wfx_w, wix_w, wox_w, wcx_w, wfx_b, wix_b, wox_b, wcx_b);

    // MT = (Wr @ wym)^T, interleaved columns
    gemm_comb<<<dim3(R_ / 128, H_ / 128), 256>>>(
        wym_w, tfy_w, tiy_w, toy_w, tcy_w);

    // persistent sequential recurrence (needs >48KB dynamic smem)
    // not stream-ordered; safe (and deterministic) to call every launch
    cudaFuncSetAttribute(lstm_rec, cudaFuncAttributeMaxDynamicSharedMemorySize, SM_TOT);
    lstm_rec<<<NBLK, 256, SM_TOT>>>(out);
}

// round 6
// speedup vs baseline: 1.1806x; 1.1806x over previous
#include <cuda_runtime.h>
#include <math.h>

typedef unsigned long long u64;

#define T_   1000
#define B_   16
#define I_   440
#define H_   1024
#define P_   512
#define R_   4096   // 4*H, column-interleaved: col = hh*4 + gate (f,i,o,c)
#define NBLK 128

// ---------------- device scratch (no runtime allocation allowed) ----------------
static __device__ float g_G[(size_t)T_ * B_ * R_];  // 262 MB: input projections [t][b][col]
static __device__ float g_MT[(size_t)H_ * R_];      // 16 MB: fused recurrent weights [k][col]
static __device__ float g_h[2][H_ * B_];            // double-buffered hidden [buf][k][b]
static __device__ unsigned g_count = 0;             // barrier arrivals (self-resetting)
static __device__ unsigned g_gen   = 0;             // barrier generation (monotonic across replays)

// ---------------- f32x2 packed-pair helpers (FFMA2 path on sm_103a) ----------------
__device__ __forceinline__ u64 pack2(float lo, float hi) {
    u64 r; asm("mov.b64 %0, {%1, %2};" : "=l"(r) : "f"(lo), "f"(hi)); return r;
}
__device__ __forceinline__ void unpack2(u64 v, float& lo, float& hi) {
    asm("mov.b64 {%0, %1}, %2;" : "=f"(lo), "=f"(hi) : "l"(v));
}
__device__ __forceinline__ u64 ffma2(u64 a, u64 b, u64 c) {
    u64 d; asm("fma.rn.f32x2 %0, %1, %2, %3;" : "=l"(d) : "l"(a), "l"(b), "l"(c)); return d;
}
__device__ __forceinline__ u64 fadd2(u64 a, u64 b) {
    u64 d; asm("add.rn.f32x2 %0, %1, %2;" : "=l"(d) : "l"(a), "l"(b)); return d;
}

// ---------------- grid barrier: scoped release/acquire, NO membar (no CCTL.IVALL) ----
// Arrive with atom.add.release.gpu; waiters spin on ld.acquire.gpu. Generation target
// is base+k where base is read at kernel entry -> safe across graph replays without
// any state reset. No gpu-scope MEMBAR is emitted, so L1 stays warm and each block's
// 128 KB MT slice survives all 1000 steps.
__device__ __forceinline__ void gsync(unsigned target) {
    __syncthreads();
    if (threadIdx.x == 0) {
        unsigned old;
        asm volatile("atom.add.release.gpu.u32 %0, [%1], %2;"
                     : "=r"(old) : "l"(&g_count), "r"(1u) : "memory");
        if (old == NBLK - 1) {
            asm volatile("st.relaxed.gpu.u32 [%0], %1;" :: "l"(&g_count), "r"(0u) : "memory");
            asm volatile("st.release.gpu.u32 [%0], %1;" :: "l"(&g_gen), "r"(target) : "memory");
        } else {
            unsigned cur;
            do {
                asm volatile("ld.acquire.gpu.u32 %0, [%1];"
                             : "=r"(cur) : "l"(&g_gen) : "memory");
            } while ((int)(cur - target) < 0);
        }
    }
    __syncthreads();
}

// =====================================================================
// Kernel 1: G[m][col] = sum_k X[m][k] * W_gate(col)[hh(col)][k] + bias
//   m = t*16+b (16000), col = hh*4+gate (4096, interleaved), k = I (440)
//   128x128 tile, BK=8, 256 threads, 8m x 8n per thread via 32 fma.f32x2.
//   As stored as plain floats; A duplicated into reg pairs via MOV (ALU pipe
//   was idle at 7%) -> LDS drops 6 -> 4 LDS.128 per kk (was the 90.7% L1 bound).
// =====================================================================
__global__ __launch_bounds__(256) void gemm_input(
    const float* __restrict__ X,
    const float* __restrict__ wf, const float* __restrict__ wi,
    const float* __restrict__ wo, const float* __restrict__ wc,
    const float* __restrict__ bf, const float* __restrict__ bi,
    const float* __restrict__ bo, const float* __restrict__ bc)
{
    __shared__ __align__(16) float As[8][128];   // 4 KB
    __shared__ __align__(16) float Bs[8][128];   // 4 KB

    const int tid = threadIdx.x;
    const int n0  = blockIdx.x * 128;       // interleaved col base (hh base = n0>>2)
    const int m0  = blockIdx.y * 128;

    const int lr = tid >> 1;                // 0..127
    const int lc = (tid & 1) * 4;           // 0 or 4

    const int bgate = lr & 3;
    const int bhh   = (n0 >> 2) + (lr >> 2);
    const float* W = (bgate == 0) ? wf : (bgate == 1) ? wi : (bgate == 2) ? wo : wc;
    const float* aptr = X + (size_t)(m0 + lr) * I_ + lc;
    const float* bptr = W + (size_t)bhh * I_ + lc;

    float4 areg = *(const float4*)aptr;
    float4 breg = *(const float4*)bptr;

    const int tm = (tid >> 4) * 8;
    const int tn = (tid & 15) * 8;

    u64 acc[8][4];
#pragma unroll
    for (int i = 0; i < 8; ++i)
#pragma unroll
        for (int j = 0; j < 4; ++j) acc[i][j] = 0ull;

    for (int k0 = 0; k0 < I_; k0 += 8) {
        As[lc + 0][lr] = areg.x; As[lc + 1][lr] = areg.y;
        As[lc + 2][lr] = areg.z; As[lc + 3][lr] = areg.w;
        Bs[lc + 0][lr] = breg.x; Bs[lc + 1][lr] = breg.y;
        Bs[lc + 2][lr] = breg.z; Bs[lc + 3][lr] = breg.w;
        __syncthreads();
        if (k0 + 8 < I_) {
            areg = *(const float4*)(aptr + k0 + 8);
            breg = *(const float4*)(bptr + k0 + 8);
        }
#pragma unroll
        for (int kk = 0; kk < 8; ++kk) {
            float4 a0 = *(const float4*)&As[kk][tm];
            float4 a1 = *(const float4*)&As[kk][tm + 4];
            u64 ad[8];
            ad[0] = pack2(a0.x, a0.x); ad[1] = pack2(a0.y, a0.y);
            ad[2] = pack2(a0.z, a0.z); ad[3] = pack2(a0.w, a0.w);
            ad[4] = pack2(a1.x, a1.x); ad[5] = pack2(a1.y, a1.y);
            ad[6] = pack2(a1.z, a1.z); ad[7] = pack2(a1.w, a1.w);
            u64 b2[4];
            *(float4*)&b2[0] = *(const float4*)&Bs[kk][tn];
            *(float4*)&b2[2] = *(const float4*)&Bs[kk][tn + 4];
#pragma unroll
            for (int i = 0; i < 8; ++i)
#pragma unroll
                for (int j = 0; j < 4; ++j)
                    acc[i][j] = ffma2(ad[i], b2[j], acc[i][j]);
        }
        __syncthreads();
    }

    // bias per column (interleaved): gate = (tn+j)&3, hh = (n0>>2)+((tn+j)>>2)
    const float* bsel[4] = {bf, bi, bo, bc};
    float bv[8];
#pragma unroll
    for (int j = 0; j < 8; ++j)
        bv[j] = bsel[(tn + j) & 3][(n0 >> 2) + ((tn + j) >> 2)];

#pragma unroll
    for (int i = 0; i < 8; ++i) {
        float cv[8];
#pragma unroll
        for (int jp = 0; jp < 4; ++jp) unpack2(acc[i][jp], cv[2 * jp], cv[2 * jp + 1]);
        float* crow = g_G + (size_t)(m0 + tm + i) * R_ + n0 + tn;
        float4 v0, v1;
        v0.x = cv[0] + bv[0]; v0.y = cv[1] + bv[1]; v0.z = cv[2] + bv[2]; v0.w = cv[3] + bv[3];
        v1.x = cv[4] + bv[4]; v1.y = cv[5] + bv[5]; v1.z = cv[6] + bv[6]; v1.w = cv[7] + bv[7];
        *(float4*)(crow)     = v0;
        *(float4*)(crow + 4) = v1;
    }
}

// =====================================================================
// Kernel 2: MT[h][col] = sum_p wym[p][h] * Wr_gate(col)[hh(col)][p]
//   Folds output projection into the recurrence. m=h (1024), col (4096), k=p (512)
// =====================================================================
__global__ __launch_bounds__(256) void gemm_comb(
    const float* __restrict__ wym,
    const float* __restrict__ tf, const float* __restrict__ ti,
    const float* __restrict__ to_, const float* __restrict__ tc)
{
    __shared__ __align__(16) float As[8][128];
    __shared__ __align__(16) float Bs[8][128];

    const int tid = threadIdx.x;
    const int n0  = blockIdx.x * 128;
    const int m0  = blockIdx.y * 128;

    const int akk = tid >> 5;
    const int amm = (tid & 31) * 4;
    const float* aptr = wym + (size_t)akk * H_ + m0 + amm;

    const int lr = tid >> 1;
    const int lc = (tid & 1) * 4;
    const int bgate = lr & 3;
    const float* Wr = (bgate == 0) ? tf : (bgate == 1) ? ti : (bgate == 2) ? to_ : tc;
    const float* bptr = Wr + (size_t)((n0 >> 2) + (lr >> 2)) * P_ + lc;

    float4 areg = *(const float4*)aptr;
    float4 breg = *(const float4*)bptr;

    const int tm = (tid >> 4) * 8;
    const int tn = (tid & 15) * 8;

    float acc[8][8];
#pragma unroll
    for (int i = 0; i < 8; ++i)
#pragma unroll
        for (int j = 0; j < 8; ++j) acc[i][j] = 0.f;

    for (int k0 = 0; k0 < P_; k0 += 8) {
        *(float4*)&As[akk][amm] = areg;
        Bs[lc + 0][lr] = breg.x; Bs[lc + 1][lr] = breg.y;
        Bs[lc + 2][lr] = breg.z; Bs[lc + 3][lr] = breg.w;
        __syncthreads();
        if (k0 + 8 < P_) {
            areg = *(const float4*)(aptr + (size_t)(k0 + 8) * H_);
            breg = *(const float4*)(bptr + k0 + 8);
        }
#pragma unroll
        for (int kk = 0; kk < 8; ++kk) {
            float a[8], b[8];
            *(float4*)(a)     = *(const float4*)&As[kk][tm];
            *(float4*)(a + 4) = *(const float4*)&As[kk][tm + 4];
            *(float4*)(b)     = *(const float4*)&Bs[kk][tn];
            *(float4*)(b + 4) = *(const float4*)&Bs[kk][tn + 4];
#pragma unroll
            for (int i = 0; i < 8; ++i)
#pragma unroll
                for (int j = 0; j < 8; ++j)
                    acc[i][j] = fmaf(a[i], b[j], acc[i][j]);
        }
        __syncthreads();
    }

#pragma unroll
    for (int i = 0; i < 8; ++i) {
        float* crow = g_MT + (size_t)(m0 + tm + i) * R_ + n0 + tn;
        *(float4*)(crow)     = make_float4(acc[i][0], acc[i][1], acc[i][2], acc[i][3]);
        *(float4*)(crow + 4) = make_float4(acc[i][4], acc[i][5], acc[i][6], acc[i][7]);
    }
}

// =====================================================================
// Kernel 3: persistent recurrence. 128 blocks x 256 threads, ONE gsync/step.
//   Block owns 8 hh-cells (32 interleaved cols) x all 16 b.
//   Warps split K=1024 (128 each), reduce partials in SMEM, block does its
//   own pointwise. h double-buffered in global (st.cg / ld.cg: L2 coherence).
//   MT slice (128 KB/block) L1-resident (barrier emits no IVALL).
//   G[t] loaded into regs at step top (latency hidden by matmul); G[t+1]
//   prefetched to L2.
// =====================================================================
__device__ __forceinline__ float sigmoidf_(float x) { return 1.f / (1.f + __expf(-x)); }

// smem layout (dynamic, 86272 B):
//  [0,      65536)  h_s  : float [1024][16]
//  [65536,  83968)  part : u64   [8][32][9]  (bp dim padded 8->9)
//  [83968,  86272)  gsm  : float [16][36]    (row padded 32->36)
#define SM_PART 65536
#define SM_GSM  83968
#define SM_TOT  86272

__global__ __launch_bounds__(256, 1) void lstm_rec(float* __restrict__ out)
{
    extern __shared__ __align__(16) char smem[];
    float* h_s  = (float*)smem;
    u64*   part = (u64*)(smem + SM_PART);
    float* gsm  = (float*)(smem + SM_GSM);

    const int tid  = threadIdx.x;
    const int bid  = blockIdx.x;
    const int wid  = tid >> 5;
    const int lane = tid & 31;

    // per-launch barrier generation base (read BEFORE this block's first arrival;
    // no release can occur until all blocks arrive, so this is race-free)
    unsigned base = 0;
    if (tid == 0)
        asm volatile("ld.relaxed.gpu.u32 %0, [%1];" : "=r"(base) : "l"(&g_gen) : "memory");

    // zero both h buffers (exactly covers 2*1024*16 elements), L2-visible stores
    {
        int i = bid * 256 + tid;
        __stcg(&((float*)g_h)[i], 0.f);
    }
    gsync(base + 1);

    const int hh0 = bid * 8;                 // this block's hh cells
    const int c0  = bid * 32;                // interleaved col base = hh0*4
    const int rg  = lane >> 2;               // 0..7  (4 cols each)
    const int bg  = lane & 3;                // 0..3  (4 b each)
    const int b0  = bg * 4;

    const int pb  = tid >> 3;                // pointwise: b
    const int phl = tid & 7;                 //            hh local
    float cstate = 0.f;                      // cell state (tid<128 own one cell)

    const float* MTbase = g_MT + (size_t)(wid * 128) * R_ + c0 + rg * 4;
    const float* Gbase  = g_G + (size_t)pb * R_ + (size_t)(hh0 + phl) * 4;

    for (int t = 0; t < T_; ++t) {
        // ---- load this step's G slice into regs (latency hidden by matmul) ----
        float4 gg;
        if (tid < 128)
            gg = __ldcs((const float4*)(Gbase + (size_t)t * B_ * R_));

        // ---- each warp stages its own K-chunk of h (L2 loads, no L1 pollution) ----
        // warp chunk = 128 k x 16 b = 2048 floats = 512 float4 = 16 iters x 32 lanes
        {
            const float4* src = (const float4*)(&g_h[t & 1][wid * 128 * 16]);
            float4* dst = (float4*)(&h_s[wid * 128 * 16]);
#pragma unroll
            for (int i = 0; i < 16; ++i) {
                int idx = i * 32 + lane;
                dst[idx] = __ldcg(src + idx);
            }
            __syncwarp();
        }

        // ---- matmul over this warp's K-chunk: 4 cols x 16 b per lane ----
        u64 acc[4][2];
#pragma unroll
        for (int i = 0; i < 4; ++i) { acc[i][0] = 0ull; acc[i][1] = 0ull; }

        const float* mp = MTbase;
        const float* hp = &h_s[wid * 128 * 16 + b0];
#pragma unroll 4
        for (int kk = 0; kk < 128; ++kk) {
            float4 m = *(const float4*)mp;     // L1-resident MT
            mp += R_;
            u64 hv[2];
            *(float4*)hv = *(const float4*)hp;
            hp += 16;
            u64 mm;
            mm = pack2(m.x, m.x);
            acc[0][0] = ffma2(mm, hv[0], acc[0][0]); acc[0][1] = ffma2(mm, hv[1], acc[0][1]);
            mm = pack2(m.y, m.y);
            acc[1][0] = ffma2(mm, hv[0], acc[1][0]); acc[1][1] = ffma2(mm, hv[1], acc[1][1]);
            mm = pack2(m.z, m.z);
            acc[2][0] = ffma2(mm, hv[0], acc[2][0]); acc[2][1] = ffma2(mm, hv[1], acc[2][1]);
            mm = pack2(m.w, m.w);
            acc[3][0] = ffma2(mm, hv[0], acc[3][0]); acc[3][1] = ffma2(mm, hv[1], acc[3][1]);
        }

        // ---- warp partials -> smem ----
#pragma unroll
        for (int i = 0; i < 4; ++i) {
#pragma unroll
            for (int j = 0; j < 2; ++j)
                part[(size_t)(wid * 32 + rg * 4 + i) * 9 + bg * 2 + j] = acc[i][j];
        }
        __syncthreads();

        // ---- reduce 8 warp partials; scatter to gsm[b][ci] ----
        {
            const int ri = tid >> 3;        // column index within block (0..31)
            const int bp = tid & 7;         // b-pair index (b = 2bp, 2bp+1)
            u64 s = part[(size_t)ri * 9 + bp];
#pragma unroll
            for (int w = 1; w < 8; ++w)
                s = fadd2(s, part[(size_t)(w * 32 + ri) * 9 + bp]);
            float lo, hi;
            unpack2(s, lo, hi);
            gsm[(2 * bp) * 36 + ri]     = lo;
            gsm[(2 * bp + 1) * 36 + ri] = hi;
        }
        __syncthreads();

        // ---- pointwise LSTM update for owned cells ----
        if (tid < 128) {
            float4 gd = *(const float4*)&gsm[pb * 36 + phl * 4];
            float zf = gg.x + gd.x;
            float zi = gg.y + gd.y;
            float zo = gg.z + gd.z;
            float zc = gg.w + gd.w;
            float ft = sigmoidf_(zf);
            float it = sigmoidf_(zi);
            float ot = sigmoidf_(zo);
            cstate = it * tanhf(zc) + ft * cstate;
            float h = ot * tanhf(cstate);
            __stcg(&g_h[(t + 1) & 1][(hh0 + phl) * 16 + pb], h);
            __stcs(&out[((size_t)(t * B_ + pb) << 10) + hh0 + phl], h);
            // warm L2 for the next step's G slice
            if (t + 1 < T_) {
                const float* np = Gbase + (size_t)(t + 1) * B_ * R_;
                asm volatile("prefetch.global.L2 [%0];" :: "l"(np));
            }
        }

        gsync(base + 2 + t);   // all h writes L2-visible before anyone stages next step
    }
}

// =====================================================================
// launch
// =====================================================================
extern "C" void kernel_launch(void* const* d_in, const int* in_sizes, int n_in,
                              void* d_out, int out_size)
{
    const float* x     = (const float*)d_in[0];
    const float* wfx_w = (const float*)d_in[1];
    const float* wfx_b = (const float*)d_in[2];
    const float* wix_w = (const float*)d_in[3];
    const float* wix_b = (const float*)d_in[4];
    const float* wox_w = (const float*)d_in[5];
    const float* wox_b = (const float*)d_in[6];
    const float* wcx_w = (const float*)d_in[7];
    const float* wcx_b = (const float*)d_in[8];
    const float* tfy_w = (const float*)d_in[9];
    const float* tiy_w = (const float*)d_in[10];
    const float* toy_w = (const float*)d_in[11];
    const float* tcy_w = (const float*)d_in[12];
    const float* wym_w = (const float*)d_in[13];
    float* out = (float*)d_out;

    // G = x @ Wx^T + b, interleaved columns (all timesteps)
    gemm_input<<<dim3(R_ / 128, 16000 / 128), 256>>>(
        x, wfx_w, wix_w, wox_w, wcx_w, wfx_b, wix_b, wox_b, wcx_b);

    // MT = (Wr @ wym)^T, interleaved columns
    gemm_comb<<<dim3(R_ / 128, H_ / 128), 256>>>(
        wym_w, tfy_w, tiy_w, toy_w, tcy_w);

    // persistent sequential recurrence (needs >48KB dynamic smem)
    cudaFuncSetAttribute(lstm_rec, cudaFuncAttributeMaxDynamicSharedMemorySize, SM_TOT);
    lstm_rec<<<NBLK, 256, SM_TOT>>>(out);
}

// round 7
// speedup vs baseline: 1.2024x; 1.0185x over previous
#include <cuda_runtime.h>
#include <math.h>

typedef unsigned long long u64;

#define T_   1000
#define B_   16
#define I_   440
#define H_   1024
#define P_   512
#define R_   4096   // 4*H, column-interleaved: col = hh*4 + gate (f,i,o,c)
#define NBLK 128
#define MTBLK (H_ * 32)   // 32768 floats: one block's contiguous MT slice

// ---------------- device scratch (no runtime allocation allowed) ----------------
static __device__ float g_G[(size_t)T_ * B_ * R_];  // 262 MB: input projections [t][b][col]
static __device__ float g_MT[(size_t)H_ * R_];      // 16 MB: fused recurrent weights,
                                                    //   BLOCK-CONTIGUOUS: [col>>5][k][col&31]
static __device__ float g_h[2][H_ * B_];            // double-buffered hidden [buf][k][b]
static __device__ unsigned g_count = 0;             // barrier arrivals (self-resetting)
static __device__ unsigned g_gen   = 0;             // barrier generation (monotonic across replays)

// ---------------- f32x2 packed-pair helpers (FFMA2 path on sm_103a) ----------------
__device__ __forceinline__ u64 pack2(float lo, float hi) {
    u64 r; asm("mov.b64 %0, {%1, %2};" : "=l"(r) : "f"(lo), "f"(hi)); return r;
}
__device__ __forceinline__ void unpack2(u64 v, float& lo, float& hi) {
    asm("mov.b64 {%0, %1}, %2;" : "=f"(lo), "=f"(hi) : "l"(v));
}
__device__ __forceinline__ u64 ffma2(u64 a, u64 b, u64 c) {
    u64 d; asm("fma.rn.f32x2 %0, %1, %2, %3;" : "=l"(d) : "l"(a), "l"(b), "l"(c)); return d;
}
__device__ __forceinline__ u64 fadd2(u64 a, u64 b) {
    u64 d; asm("add.rn.f32x2 %0, %1, %2;" : "=l"(d) : "l"(a), "l"(b)); return d;
}

// ---------------- grid barrier: scoped release/acquire, NO membar (no CCTL.IVALL) ----
__device__ __forceinline__ void gsync(unsigned target) {
    __syncthreads();
    if (threadIdx.x == 0) {
        unsigned old;
        asm volatile("atom.add.release.gpu.u32 %0, [%1], %2;"
                     : "=r"(old) : "l"(&g_count), "r"(1u) : "memory");
        if (old == NBLK - 1) {
            asm volatile("st.relaxed.gpu.u32 [%0], %1;" :: "l"(&g_count), "r"(0u) : "memory");
            asm volatile("st.release.gpu.u32 [%0], %1;" :: "l"(&g_gen), "r"(target) : "memory");
        } else {
            unsigned cur;
            do {
                asm volatile("ld.acquire.gpu.u32 %0, [%1];"
                             : "=r"(cur) : "l"(&g_gen) : "memory");
            } while ((int)(cur - target) < 0);
        }
    }
    __syncthreads();
}

// =====================================================================
// Kernel 1: G[m][col] = sum_k X[m][k] * W_gate(col)[hh(col)][k] + bias
//   (unchanged from R5: measured 1.305 ms; kept fixed to isolate this
//    round's MT-layout variable)
// =====================================================================
__global__ __launch_bounds__(256) void gemm_input(
    const float* __restrict__ X,
    const float* __restrict__ wf, const float* __restrict__ wi,
    const float* __restrict__ wo, const float* __restrict__ wc,
    const float* __restrict__ bf, const float* __restrict__ bi,
    const float* __restrict__ bo, const float* __restrict__ bc)
{
    __shared__ __align__(16) float As[8][128];
    __shared__ __align__(16) float Bs[8][128];

    const int tid = threadIdx.x;
    const int n0  = blockIdx.x * 128;
    const int m0  = blockIdx.y * 128;

    const int lr = tid >> 1;
    const int lc = (tid & 1) * 4;

    const int bgate = lr & 3;
    const int bhh   = (n0 >> 2) + (lr >> 2);
    const float* W = (bgate == 0) ? wf : (bgate == 1) ? wi : (bgate == 2) ? wo : wc;
    const float* aptr = X + (size_t)(m0 + lr) * I_ + lc;
    const float* bptr = W + (size_t)bhh * I_ + lc;

    float4 areg = *(const float4*)aptr;
    float4 breg = *(const float4*)bptr;

    const int tm = (tid >> 4) * 8;
    const int tn = (tid & 15) * 8;

    u64 acc[8][4];
#pragma unroll
    for (int i = 0; i < 8; ++i)
#pragma unroll
        for (int j = 0; j < 4; ++j) acc[i][j] = 0ull;

    for (int k0 = 0; k0 < I_; k0 += 8) {
        As[lc + 0][lr] = areg.x; As[lc + 1][lr] = areg.y;
        As[lc + 2][lr] = areg.z; As[lc + 3][lr] = areg.w;
        Bs[lc + 0][lr] = breg.x; Bs[lc + 1][lr] = breg.y;
        Bs[lc + 2][lr] = breg.z; Bs[lc + 3][lr] = breg.w;
        __syncthreads();
        if (k0 + 8 < I_) {
            areg = *(const float4*)(aptr + k0 + 8);
            breg = *(const float4*)(bptr + k0 + 8);
        }
#pragma unroll
        for (int kk = 0; kk < 8; ++kk) {
            float4 a0 = *(const float4*)&As[kk][tm];
            float4 a1 = *(const float4*)&As[kk][tm + 4];
            u64 ad[8];
            ad[0] = pack2(a0.x, a0.x); ad[1] = pack2(a0.y, a0.y);
            ad[2] = pack2(a0.z, a0.z); ad[3] = pack2(a0.w, a0.w);
            ad[4] = pack2(a1.x, a1.x); ad[5] = pack2(a1.y, a1.y);
            ad[6] = pack2(a1.z, a1.z); ad[7] = pack2(a1.w, a1.w);
            u64 b2[4];
            *(float4*)&b2[0] = *(const float4*)&Bs[kk][tn];
            *(float4*)&b2[2] = *(const float4*)&Bs[kk][tn + 4];
#pragma unroll
            for (int i = 0; i < 8; ++i)
#pragma unroll
                for (int j = 0; j < 4; ++j)
                    acc[i][j] = ffma2(ad[i], b2[j], acc[i][j]);
        }
        __syncthreads();
    }

    const float* bsel[4] = {bf, bi, bo, bc};
    float bv[8];
#pragma unroll
    for (int j = 0; j < 8; ++j)
        bv[j] = bsel[(tn + j) & 3][(n0 >> 2) + ((tn + j) >> 2)];

#pragma unroll
    for (int i = 0; i < 8; ++i) {
        float cv[8];
#pragma unroll
        for (int jp = 0; jp < 4; ++jp) unpack2(acc[i][jp], cv[2 * jp], cv[2 * jp + 1]);
        float* crow = g_G + (size_t)(m0 + tm + i) * R_ + n0 + tn;
        float4 v0, v1;
        v0.x = cv[0] + bv[0]; v0.y = cv[1] + bv[1]; v0.z = cv[2] + bv[2]; v0.w = cv[3] + bv[3];
        v1.x = cv[4] + bv[4]; v1.y = cv[5] + bv[5]; v1.z = cv[6] + bv[6]; v1.w = cv[7] + bv[7];
        *(float4*)(crow)     = v0;
        *(float4*)(crow + 4) = v1;
    }
}

// =====================================================================
// Kernel 2: MT[blk][k][cl] = sum_p wym[p][h(col)] * Wr_gate(col)[hh(col)][p]
//   where col = blk*32 + cl. BLOCK-CONTIGUOUS output layout: each lstm_rec
//   block's 128 KB slice is one contiguous range -> L1 sets used uniformly
//   (old [k][col] layout had 16 KB row stride -> only 128 L1 sets -> thrash).
// =====================================================================
__global__ __launch_bounds__(256) void gemm_comb(
    const float* __restrict__ wym,
    const float* __restrict__ tf, const float* __restrict__ ti,
    const float* __restrict__ to_, const float* __restrict__ tc)
{
    __shared__ __align__(16) float As[8][128];
    __shared__ __align__(16) float Bs[8][128];

    const int tid = threadIdx.x;
    const int n0  = blockIdx.x * 128;
    const int m0  = blockIdx.y * 128;

    const int akk = tid >> 5;
    const int amm = (tid & 31) * 4;
    const float* aptr = wym + (size_t)akk * H_ + m0 + amm;

    const int lr = tid >> 1;
    const int lc = (tid & 1) * 4;
    const int bgate = lr & 3;
    const float* Wr = (bgate == 0) ? tf : (bgate == 1) ? ti : (bgate == 2) ? to_ : tc;
    const float* bptr = Wr + (size_t)((n0 >> 2) + (lr >> 2)) * P_ + lc;

    float4 areg = *(const float4*)aptr;
    float4 breg = *(const float4*)bptr;

    const int tm = (tid >> 4) * 8;
    const int tn = (tid & 15) * 8;

    float acc[8][8];
#pragma unroll
    for (int i = 0; i < 8; ++i)
#pragma unroll
        for (int j = 0; j < 8; ++j) acc[i][j] = 0.f;

    for (int k0 = 0; k0 < P_; k0 += 8) {
        *(float4*)&As[akk][amm] = areg;
        Bs[lc + 0][lr] = breg.x; Bs[lc + 1][lr] = breg.y;
        Bs[lc + 2][lr] = breg.z; Bs[lc + 3][lr] = breg.w;
        __syncthreads();
        if (k0 + 8 < P_) {
            areg = *(const float4*)(aptr + (size_t)(k0 + 8) * H_);
            breg = *(const float4*)(bptr + k0 + 8);
        }
#pragma unroll
        for (int kk = 0; kk < 8; ++kk) {
            float a[8], b[8];
            *(float4*)(a)     = *(const float4*)&As[kk][tm];
            *(float4*)(a + 4) = *(const float4*)&As[kk][tm + 4];
            *(float4*)(b)     = *(const float4*)&Bs[kk][tn];
            *(float4*)(b + 4) = *(const float4*)&Bs[kk][tn + 4];
#pragma unroll
            for (int i = 0; i < 8; ++i)
#pragma unroll
                for (int j = 0; j < 8; ++j)
                    acc[i][j] = fmaf(a[i], b[j], acc[i][j]);
        }
        __syncthreads();
    }

    // block-contiguous store: col group [n0+tn, n0+tn+8) sits in ONE 32-col block
    // (tn multiple of 8, 8 | 32), at offset blk*MTBLK + k*32 + (col&31)
    {
        const int colbase = n0 + tn;
        const int blk = colbase >> 5;
        const int cl  = colbase & 31;
#pragma unroll
        for (int i = 0; i < 8; ++i) {
            float* crow = g_MT + (size_t)blk * MTBLK + (size_t)(m0 + tm + i) * 32 + cl;
            *(float4*)(crow)     = make_float4(acc[i][0], acc[i][1], acc[i][2], acc[i][3]);
            *(float4*)(crow + 4) = make_float4(acc[i][4], acc[i][5], acc[i][6], acc[i][7]);
        }
    }
}

// =====================================================================
// Kernel 3: persistent recurrence. 128 blocks x 256 threads, ONE gsync/step.
//   Block bid reads its CONTIGUOUS 128 KB MT slice g_MT[bid*MTBLK ...]:
//   row k = 32 floats = one 128 B line, line-sequential in k -> L1-resident.
// =====================================================================
__device__ __forceinline__ float sigmoidf_(float x) { return 1.f / (1.f + __expf(-x)); }

// smem layout (dynamic, 86272 B):
//  [0,      65536)  h_s  : float [1024][16]
//  [65536,  83968)  part : u64   [8][32][9]  (bp dim padded 8->9)
//  [83968,  86272)  gsm  : float [16][36]    (row padded 32->36)
#define SM_PART 65536
#define SM_GSM  83968
#define SM_TOT  86272

__global__ __launch_bounds__(256, 1) void lstm_rec(float* __restrict__ out)
{
    extern __shared__ __align__(16) char smem[];
    float* h_s  = (float*)smem;
    u64*   part = (u64*)(smem + SM_PART);
    float* gsm  = (float*)(smem + SM_GSM);

    const int tid  = threadIdx.x;
    const int bid  = blockIdx.x;
    const int wid  = tid >> 5;
    const int lane = tid & 31;

    unsigned base = 0;
    if (tid == 0)
        asm volatile("ld.relaxed.gpu.u32 %0, [%1];" : "=r"(base) : "l"(&g_gen) : "memory");

    {
        int i = bid * 256 + tid;
        __stcg(&((float*)g_h)[i], 0.f);
    }
    gsync(base + 1);

    const int hh0 = bid * 8;
    const int rg  = lane >> 2;               // 0..7  (4 cols each)
    const int bg  = lane & 3;                // 0..3  (4 b each)
    const int b0  = bg * 4;

    const int pb  = tid >> 3;
    const int phl = tid & 7;
    float cstate = 0.f;

    // contiguous slice: this block's 128 KB at g_MT + bid*MTBLK; row k = 32 floats
    const float* MTbase = g_MT + (size_t)bid * MTBLK + (size_t)(wid * 128) * 32 + rg * 4;
    const float* Gbase  = g_G + (size_t)pb * R_ + (size_t)(hh0 + phl) * 4;

    for (int t = 0; t < T_; ++t) {
        float4 gg;
        if (tid < 128)
            gg = __ldcs((const float4*)(Gbase + (size_t)t * B_ * R_));

        {
            const float4* src = (const float4*)(&g_h[t & 1][wid * 128 * 16]);
            float4* dst = (float4*)(&h_s[wid * 128 * 16]);
#pragma unroll
            for (int i = 0; i < 16; ++i) {
                int idx = i * 32 + lane;
                dst[idx] = __ldcg(src + idx);
            }
            __syncwarp();
        }

        u64 acc[4][2];
#pragma unroll
        for (int i = 0; i < 4; ++i) { acc[i][0] = 0ull; acc[i][1] = 0ull; }

        const float* mp = MTbase;
        const float* hp = &h_s[wid * 128 * 16 + b0];
#pragma unroll 4
        for (int kk = 0; kk < 128; ++kk) {
            float4 m = *(const float4*)mp;     // L1-resident contiguous MT
            mp += 32;
            u64 hv[2];
            *(float4*)hv = *(const float4*)hp;
            hp += 16;
            u64 mm;
            mm = pack2(m.x, m.x);
            acc[0][0] = ffma2(mm, hv[0], acc[0][0]); acc[0][1] = ffma2(mm, hv[1], acc[0][1]);
            mm = pack2(m.y, m.y);
            acc[1][0] = ffma2(mm, hv[0], acc[1][0]); acc[1][1] = ffma2(mm, hv[1], acc[1][1]);
            mm = pack2(m.z, m.z);
            acc[2][0] = ffma2(mm, hv[0], acc[2][0]); acc[2][1] = ffma2(mm, hv[1], acc[2][1]);
            mm = pack2(m.w, m.w);
            acc[3][0] = ffma2(mm, hv[0], acc[3][0]); acc[3][1] = ffma2(mm, hv[1], acc[3][1]);
        }

#pragma unroll
        for (int i = 0; i < 4; ++i) {
#pragma unroll
            for (int j = 0; j < 2; ++j)
                part[(size_t)(wid * 32 + rg * 4 + i) * 9 + bg * 2 + j] = acc[i][j];
        }
        __syncthreads();

        {
            const int ri = tid >> 3;
            const int bp = tid & 7;
            u64 s = part[(size_t)ri * 9 + bp];
#pragma unroll
            for (int w = 1; w < 8; ++w)
                s = fadd2(s, part[(size_t)(w * 32 + ri) * 9 + bp]);
            float lo, hi;
            unpack2(s, lo, hi);
            gsm[(2 * bp) * 36 + ri]     = lo;
            gsm[(2 * bp + 1) * 36 + ri] = hi;
        }
        __syncthreads();

        if (tid < 128) {
            float4 gd = *(const float4*)&gsm[pb * 36 + phl * 4];
            float zf = gg.x + gd.x;
            float zi = gg.y + gd.y;
            float zo = gg.z + gd.z;
            float zc = gg.w + gd.w;
            float ft = sigmoidf_(zf);
            float it = sigmoidf_(zi);
            float ot = sigmoidf_(zo);
            cstate = it * tanhf(zc) + ft * cstate;
            float h = ot * tanhf(cstate);
            __stcg(&g_h[(t + 1) & 1][(hh0 + phl) * 16 + pb], h);
            __stcs(&out[((size_t)(t * B_ + pb) << 10) + hh0 + phl], h);
            if (t + 1 < T_) {
                const float* np = Gbase + (size_t)(t + 1) * B_ * R_;
                asm volatile("prefetch.global.L2 [%0];" :: "l"(np));
            }
        }

        gsync(base + 2 + t);
    }
}

// =====================================================================
// launch
// =====================================================================
extern "C" void kernel_launch(void* const* d_in, const int* in_sizes, int n_in,
                              void* d_out, int out_size)
{
    const float* x     = (const float*)d_in[0];
    const float* wfx_w = (const float*)d_in[1];
    const float* wfx_b = (const float*)d_in[2];
    const float* wix_w = (const float*)d_in[3];
    const float* wix_b = (const float*)d_in[4];
    const float* wox_w = (const float*)d_in[5];
    const float* wox_b = (const float*)d_in[6];
    const float* wcx_w = (const float*)d_in[7];
    const float* wcx_b = (const float*)d_in[8];
    const float* tfy_w = (const float*)d_in[9];
    const float* tiy_w = (const float*)d_in[10];
    const float* toy_w = (const float*)d_in[11];
    const float* tcy_w = (const float*)d_in[12];
    const float* wym_w = (const float*)d_in[13];
    float* out = (float*)d_out;

    gemm_input<<<dim3(R_ / 128, 16000 / 128), 256>>>(
        x, wfx_w, wix_w, wox_w, wcx_w, wfx_b, wix_b, wox_b, wcx_b);

    gemm_comb<<<dim3(R_ / 128, H_ / 128), 256>>>(
        wym_w, tfy_w, tiy_w, toy_w, tcy_w);

    cudaFuncSetAttribute(lstm_rec, cudaFuncAttributeMaxDynamicSharedMemorySize, SM_TOT);
    lstm_rec<<<NBLK, 256, SM_TOT>>>(out);
}

// round 8
// speedup vs baseline: 2.1926x; 1.8235x over previous
#include <cuda_runtime.h>
#include <math.h>

typedef unsigned long long u64;
typedef unsigned int u32;

#define T_   1000
#define B_   16
#define I_   440
#define H_   1024
#define P_   512
#define R_   4096   // 4*H, column-interleaved: col = hh*4 + gate (f,i,o,c)
#define NBLK 128

// ---------------- device scratch (no runtime allocation allowed) ----------------
static __device__ float g_G[(size_t)T_ * B_ * R_];  // 262 MB: input projections [t][b][col]
// A-fragment array for mma: [block][warp][kt][mt][term(hi/lo)][lane*4+r] (u32 bf16x2)
static __device__ u32   g_Af[(size_t)NBLK * 8 * 8 * 2 * 2 * 128];   // 16 MB
static __device__ float g_h[2][H_ * B_];            // double-buffered hidden [buf][k][b]
static __device__ unsigned g_count = 0;             // barrier arrivals (self-resetting)
static __device__ unsigned g_gen   = 0;             // barrier generation (monotonic)

// ---------------- f32x2 helpers (for gemm_input + reduction) ----------------
__device__ __forceinline__ u64 pack2(float lo, float hi) {
    u64 r; asm("mov.b64 %0, {%1, %2};" : "=l"(r) : "f"(lo), "f"(hi)); return r;
}
__device__ __forceinline__ void unpack2(u64 v, float& lo, float& hi) {
    asm("mov.b64 {%0, %1}, %2;" : "=f"(lo), "=f"(hi) : "l"(v));
}
__device__ __forceinline__ u64 ffma2(u64 a, u64 b, u64 c) {
    u64 d; asm("fma.rn.f32x2 %0, %1, %2, %3;" : "=l"(d) : "l"(a), "l"(b), "l"(c)); return d;
}
__device__ __forceinline__ u64 fadd2(u64 a, u64 b) {
    u64 d; asm("add.rn.f32x2 %0, %1, %2;" : "=l"(d) : "l"(a), "l"(b)); return d;
}

// pack two f32 into bf16x2: lo 16 bits = first arg, hi 16 bits = second arg
__device__ __forceinline__ u32 bf16x2_of(float lo_elem, float hi_elem) {
    u32 d; asm("cvt.rn.bf16x2.f32 %0, %1, %2;" : "=r"(d) : "f"(hi_elem), "f"(lo_elem));
    return d;
}

// mma.sync m16n8k16 bf16 -> f32 accum (row.col)
#define MMA_BF16(d, a, b) \
    asm volatile( \
        "mma.sync.aligned.m16n8k16.row.col.f32.bf16.bf16.f32 " \
        "{%0,%1,%2,%3}, {%4,%5,%6,%7}, {%8,%9}, {%0,%1,%2,%3};\n" \
        : "+f"((d)[0]), "+f"((d)[1]), "+f"((d)[2]), "+f"((d)[3]) \
        : "r"((a)[0]), "r"((a)[1]), "r"((a)[2]), "r"((a)[3]), \
          "r"((b)[0]), "r"((b)[1]))

// ---------------- grid barrier: scoped release/acquire, NO membar (no CCTL.IVALL) ----
__device__ __forceinline__ void gsync(unsigned target) {
    __syncthreads();
    if (threadIdx.x == 0) {
        unsigned old;
        asm volatile("atom.add.release.gpu.u32 %0, [%1], %2;"
                     : "=r"(old) : "l"(&g_count), "r"(1u) : "memory");
        if (old == NBLK - 1) {
            asm volatile("st.relaxed.gpu.u32 [%0], %1;" :: "l"(&g_count), "r"(0u) : "memory");
            asm volatile("st.release.gpu.u32 [%0], %1;" :: "l"(&g_gen), "r"(target) : "memory");
        } else {
            unsigned cur;
            do {
                asm volatile("ld.acquire.gpu.u32 %0, [%1];"
                             : "=r"(cur) : "l"(&g_gen) : "memory");
            } while ((int)(cur - target) < 0);
        }
    }
    __syncthreads();
}

// =====================================================================
// Kernel 1: G[m][col] = sum_k X[m][k] * W_gate(col)[hh(col)][k] + bias
//   (unchanged: 1.306 ms measured; isolated from this round's variable)
// =====================================================================
__global__ __launch_bounds__(256) void gemm_input(
    const float* __restrict__ X,
    const float* __restrict__ wf, const float* __restrict__ wi,
    const float* __restrict__ wo, const float* __restrict__ wc,
    const float* __restrict__ bf, const float* __restrict__ bi,
    const float* __restrict__ bo, const float* __restrict__ bc)
{
    __shared__ __align__(16) float As[8][128];
    __shared__ __align__(16) float Bs[8][128];

    const int tid = threadIdx.x;
    const int n0  = blockIdx.x * 128;
    const int m0  = blockIdx.y * 128;

    const int lr = tid >> 1;
    const int lc = (tid & 1) * 4;

    const int bgate = lr & 3;
    const int bhh   = (n0 >> 2) + (lr >> 2);
    const float* W = (bgate == 0) ? wf : (bgate == 1) ? wi : (bgate == 2) ? wo : wc;
    const float* aptr = X + (size_t)(m0 + lr) * I_ + lc;
    const float* bptr = W + (size_t)bhh * I_ + lc;

    float4 areg = *(const float4*)aptr;
    float4 breg = *(const float4*)bptr;

    const int tm = (tid >> 4) * 8;
    const int tn = (tid & 15) * 8;

    u64 acc[8][4];
#pragma unroll
    for (int i = 0; i < 8; ++i)
#pragma unroll
        for (int j = 0; j < 4; ++j) acc[i][j] = 0ull;

    for (int k0 = 0; k0 < I_; k0 += 8) {
        As[lc + 0][lr] = areg.x; As[lc + 1][lr] = areg.y;
        As[lc + 2][lr] = areg.z; As[lc + 3][lr] = areg.w;
        Bs[lc + 0][lr] = breg.x; Bs[lc + 1][lr] = breg.y;
        Bs[lc + 2][lr] = breg.z; Bs[lc + 3][lr] = breg.w;
        __syncthreads();
        if (k0 + 8 < I_) {
            areg = *(const float4*)(aptr + k0 + 8);
            breg = *(const float4*)(bptr + k0 + 8);
        }
#pragma unroll
        for (int kk = 0; kk < 8; ++kk) {
            float4 a0 = *(const float4*)&As[kk][tm];
            float4 a1 = *(const float4*)&As[kk][tm + 4];
            u64 ad[8];
            ad[0] = pack2(a0.x, a0.x); ad[1] = pack2(a0.y, a0.y);
            ad[2] = pack2(a0.z, a0.z); ad[3] = pack2(a0.w, a0.w);
            ad[4] = pack2(a1.x, a1.x); ad[5] = pack2(a1.y, a1.y);
            ad[6] = pack2(a1.z, a1.z); ad[7] = pack2(a1.w, a1.w);
            u64 b2[4];
            *(float4*)&b2[0] = *(const float4*)&Bs[kk][tn];
            *(float4*)&b2[2] = *(const float4*)&Bs[kk][tn + 4];
#pragma unroll
            for (int i = 0; i < 8; ++i)
#pragma unroll
                for (int j = 0; j < 4; ++j)
                    acc[i][j] = ffma2(ad[i], b2[j], acc[i][j]);
        }
        __syncthreads();
    }

    const float* bsel[4] = {bf, bi, bo, bc};
    float bv[8];
#pragma unroll
    for (int j = 0; j < 8; ++j)
        bv[j] = bsel[(tn + j) & 3][(n0 >> 2) + ((tn + j) >> 2)];

#pragma unroll
    for (int i = 0; i < 8; ++i) {
        float cv[8];
#pragma unroll
        for (int jp = 0; jp < 4; ++jp) unpack2(acc[i][jp], cv[2 * jp], cv[2 * jp + 1]);
        float* crow = g_G + (size_t)(m0 + tm + i) * R_ + n0 + tn;
        float4 v0, v1;
        v0.x = cv[0] + bv[0]; v0.y = cv[1] + bv[1]; v0.z = cv[2] + bv[2]; v0.w = cv[3] + bv[3];
        v1.x = cv[4] + bv[4]; v1.y = cv[5] + bv[5]; v1.z = cv[6] + bv[6]; v1.w = cv[7] + bv[7];
        *(float4*)(crow)     = v0;
        *(float4*)(crow + 4) = v1;
    }
}

// =====================================================================
// Kernel 2: M[col][k] = sum_p wym[p][k] * Wr_gate(col)[hh(col)][p],
//   emitted as split-bf16 (hi+lo) mma A-FRAGMENTS:
//   A[m=col][k], frag layout (m16n8k16): lane = (col%8)*4 + (k%8)/2,
//   reg r = ((col>>3)&1) + 2*((k>>3)&1), bf16x2 packs (k even, k+1).
// =====================================================================
__global__ __launch_bounds__(256) void gemm_comb(
    const float* __restrict__ wym,
    const float* __restrict__ tf, const float* __restrict__ ti,
    const float* __restrict__ to_, const float* __restrict__ tc)
{
    __shared__ __align__(16) float As[8][128];
    __shared__ __align__(16) float Bs[8][128];

    const int tid = threadIdx.x;
    const int n0  = blockIdx.x * 128;   // cols
    const int m0  = blockIdx.y * 128;   // k

    const int akk = tid >> 5;
    const int amm = (tid & 31) * 4;
    const float* aptr = wym + (size_t)akk * H_ + m0 + amm;

    const int lr = tid >> 1;
    const int lc = (tid & 1) * 4;
    const int bgate = lr & 3;
    const float* Wr = (bgate == 0) ? tf : (bgate == 1) ? ti : (bgate == 2) ? to_ : tc;
    const float* bptr = Wr + (size_t)((n0 >> 2) + (lr >> 2)) * P_ + lc;

    float4 areg = *(const float4*)aptr;
    float4 breg = *(const float4*)bptr;

    const int tm = (tid >> 4) * 8;
    const int tn = (tid & 15) * 8;

    float acc[8][8];   // acc[i][j] = M[col=n0+tn+j][k=m0+tm+i]
#pragma unroll
    for (int i = 0; i < 8; ++i)
#pragma unroll
        for (int j = 0; j < 8; ++j) acc[i][j] = 0.f;

    for (int k0 = 0; k0 < P_; k0 += 8) {
        *(float4*)&As[akk][amm] = areg;
        Bs[lc + 0][lr] = breg.x; Bs[lc + 1][lr] = breg.y;
        Bs[lc + 2][lr] = breg.z; Bs[lc + 3][lr] = breg.w;
        __syncthreads();
        if (k0 + 8 < P_) {
            areg = *(const float4*)(aptr + (size_t)(k0 + 8) * H_);
            breg = *(const float4*)(bptr + k0 + 8);
        }
#pragma unroll
        for (int kk = 0; kk < 8; ++kk) {
            float a[8], b[8];
            *(float4*)(a)     = *(const float4*)&As[kk][tm];
            *(float4*)(a + 4) = *(const float4*)&As[kk][tm + 4];
            *(float4*)(b)     = *(const float4*)&Bs[kk][tn];
            *(float4*)(b + 4) = *(const float4*)&Bs[kk][tn + 4];
#pragma unroll
            for (int i = 0; i < 8; ++i)
#pragma unroll
                for (int j = 0; j < 8; ++j)
                    acc[i][j] = fmaf(a[i], b[j], acc[i][j]);
        }
        __syncthreads();
    }

    // ---- split-bf16 fragment epilogue ----
#pragma unroll
    for (int i = 0; i < 8; i += 2) {
        const int k = m0 + tm + i;
#pragma unroll
        for (int j = 0; j < 8; ++j) {
            const int col = n0 + tn + j;
            float v0 = acc[i][j], v1 = acc[i + 1][j];
            u32 hi = bf16x2_of(v0, v1);
            float h0 = __uint_as_float(hi << 16);
            float h1 = __uint_as_float(hi & 0xFFFF0000u);
            u32 lo = bf16x2_of(v0 - h0, v1 - h1);
            const int blk  = col >> 5;
            const int warp = k >> 7;
            const int kt   = (k >> 4) & 7;
            const int mt   = (col >> 4) & 1;
            const int r    = ((col >> 3) & 1) | (((k >> 3) & 1) << 1);
            const int lane = ((col & 7) << 2) | ((k & 7) >> 1);
            size_t base = ((((size_t)(blk * 8 + warp) * 8 + kt) * 2 + mt) * 2) * 128;
            g_Af[base + lane * 4 + r]       = hi;   // term 0 (hi)
            g_Af[base + 128 + lane * 4 + r] = lo;   // term 1 (lo)
        }
    }
}

// =====================================================================
// Kernel 3: persistent recurrence, tensor-core matmul.
//   Block owns 32 cols x 16 b. Warps split K (128 each).
//   Per warp per step: 8 kt x { 4x LDG.128 A-frags, B-frags from fp32 h
//   in smem via cvt.bf16x2 + residual, 12 mma (hi*hi, hi*lo, lo*hi) }.
//   Partials reduced in smem, per-block pointwise, ONE gsync/step.
// =====================================================================
__device__ __forceinline__ float sigmoidf_(float x) { return 1.f / (1.f + __expf(-x)); }

// smem layout (dynamic, 104704 B):
//  [0,      81920)  h_s  : float [1024][20]   (b padded 16->20, conflict-free frags)
//  [81920, 102400)  part : float [8][32][20]  (b padded 16->20)
//  [102400,104704)  gsm  : float [16][36]
#define SM_PART 81920
#define SM_GSM  102400
#define SM_TOT  104704

__global__ __launch_bounds__(256, 1) void lstm_rec(float* __restrict__ out)
{
    extern __shared__ __align__(16) char smem[];
    float* h_s  = (float*)smem;
    float* part = (float*)(smem + SM_PART);
    float* gsm  = (float*)(smem + SM_GSM);

    const int tid  = threadIdx.x;
    const int bid  = blockIdx.x;
    const int wid  = tid >> 5;
    const int lane = tid & 31;

    unsigned base = 0;
    if (tid == 0)
        asm volatile("ld.relaxed.gpu.u32 %0, [%1];" : "=r"(base) : "l"(&g_gen) : "memory");

    {
        int i = bid * 256 + tid;
        __stcg(&((float*)g_h)[i], 0.f);
    }
    gsync(base + 1);

    const int hh0 = bid * 8;
    const int pb  = tid >> 3;               // pointwise: b
    const int phl = tid & 7;                //            hh local
    float cstate = 0.f;

    const u32* Afbase = g_Af + ((size_t)(bid * 8 + wid) * 8) * 2 * 2 * 128;
    const float* Gbase = g_G + (size_t)pb * R_ + (size_t)(hh0 + phl) * 4;

    const int ln4  = lane >> 2;             // l/4
    const int lm4  = lane & 3;              // l%4

    for (int t = 0; t < T_; ++t) {
        float4 gg;
        if (tid < 128)
            gg = __ldcs((const float4*)(Gbase + (size_t)t * B_ * R_));

        // ---- stage this warp's k-slice of h into padded smem [k][20] ----
        {
            const float4* src = (const float4*)(&g_h[t & 1][0]);
#pragma unroll
            for (int i = 0; i < 16; ++i) {
                int idx = wid * 512 + i * 32 + lane;
                int k  = idx >> 2, bq = idx & 3;
                float4 v = __ldcg(src + idx);
                *(float4*)&h_s[k * 20 + bq * 4] = v;
            }
            __syncwarp();
        }

        // ---- tensor-core matmul over this warp's K-slice ----
        float d[2][2][4];
#pragma unroll
        for (int mt = 0; mt < 2; ++mt)
#pragma unroll
            for (int nt = 0; nt < 2; ++nt)
#pragma unroll
                for (int q = 0; q < 4; ++q) d[mt][nt][q] = 0.f;

#pragma unroll
        for (int kt = 0; kt < 8; ++kt) {
            // A fragments (pre-swizzled): hi at +0, lo at +128
            u32 ahi[2][4], alo[2][4];
#pragma unroll
            for (int mt = 0; mt < 2; ++mt) {
                const u32* p = Afbase + ((size_t)(kt * 2 + mt) * 2) * 128 + lane * 4;
                *(uint4*)ahi[mt] = *(const uint4*)p;
                *(uint4*)alo[mt] = *(const uint4*)(p + 128);
            }
            // B fragments from fp32 h: k-pairs (k,k+1) and (k+8,k+9)
            u32 bhi[2][2], blo[2][2];
            const int kb = wid * 128 + kt * 16 + lm4 * 2;
#pragma unroll
            for (int nt = 0; nt < 2; ++nt) {
                const int n = nt * 8 + ln4;
                float f0 = h_s[(kb + 0) * 20 + n];
                float f1 = h_s[(kb + 1) * 20 + n];
                float f2 = h_s[(kb + 8) * 20 + n];
                float f3 = h_s[(kb + 9) * 20 + n];
                u32 p0 = bf16x2_of(f0, f1);
                u32 p1 = bf16x2_of(f2, f3);
                float e0 = f0 - __uint_as_float(p0 << 16);
                float e1 = f1 - __uint_as_float(p0 & 0xFFFF0000u);
                float e2 = f2 - __uint_as_float(p1 << 16);
                float e3 = f3 - __uint_as_float(p1 & 0xFFFF0000u);
                bhi[nt][0] = p0; bhi[nt][1] = p1;
                blo[nt][0] = bf16x2_of(e0, e1);
                blo[nt][1] = bf16x2_of(e2, e3);
            }
#pragma unroll
            for (int mt = 0; mt < 2; ++mt)
#pragma unroll
                for (int nt = 0; nt < 2; ++nt) {
                    MMA_BF16(d[mt][nt], ahi[mt], bhi[nt]);
                    MMA_BF16(d[mt][nt], ahi[mt], blo[nt]);
                    MMA_BF16(d[mt][nt], alo[mt], bhi[nt]);
                }
        }

        // ---- store D fragments -> part[w][col][b] ----
#pragma unroll
        for (int mt = 0; mt < 2; ++mt)
#pragma unroll
            for (int nt = 0; nt < 2; ++nt) {
                const int c0 = mt * 16 + ln4;
                const int b  = nt * 8 + lm4 * 2;
                *(float2*)&part[(wid * 32 + c0) * 20 + b] =
                    make_float2(d[mt][nt][0], d[mt][nt][1]);
                *(float2*)&part[(wid * 32 + c0 + 8) * 20 + b] =
                    make_float2(d[mt][nt][2], d[mt][nt][3]);
            }
        __syncthreads();

        // ---- reduce 8 warp partials; scatter to gsm[b][col] ----
        {
            const int ri = tid >> 3;        // col 0..31
            const int bp = tid & 7;         // b-pair
            u64 s = *(const u64*)&part[(ri) * 20 + 2 * bp];
#pragma unroll
            for (int w = 1; w < 8; ++w)
                s = fadd2(s, *(const u64*)&part[(w * 32 + ri) * 20 + 2 * bp]);
            float lo, hi;
            unpack2(s, lo, hi);
            gsm[(2 * bp) * 36 + ri]     = lo;
            gsm[(2 * bp + 1) * 36 + ri] = hi;
        }
        __syncthreads();

        // ---- pointwise LSTM update for owned cells ----
        if (tid < 128) {
            float4 gd = *(const float4*)&gsm[pb * 36 + phl * 4];
            float zf = gg.x + gd.x;
            float zi = gg.y + gd.y;
            float zo = gg.z + gd.z;
            float zc = gg.w + gd.w;
            float ft = sigmoidf_(zf);
            float it = sigmoidf_(zi);
            float ot = sigmoidf_(zo);
            cstate = it * tanhf(zc) + ft * cstate;
            float h = ot * tanhf(cstate);
            __stcg(&g_h[(t + 1) & 1][(hh0 + phl) * 16 + pb], h);
            __stcs(&out[((size_t)(t * B_ + pb) << 10) + hh0 + phl], h);
            if (t + 1 < T_) {
                const float* np = Gbase + (size_t)(t + 1) * B_ * R_;
                asm volatile("prefetch.global.L2 [%0];" :: "l"(np));
            }
        }

        gsync(base + 2 + t);
    }
}

// =====================================================================
// launch
// =====================================================================
extern "C" void kernel_launch(void* const* d_in, const int* in_sizes, int n_in,
                              void* d_out, int out_size)
{
    const float* x     = (const float*)d_in[0];
    const float* wfx_w = (const float*)d_in[1];
    const float* wfx_b = (const float*)d_in[2];
    const float* wix_w = (const float*)d_in[3];
    const float* wix_b = (const float*)d_in[4];
    const float* wox_w = (const float*)d_in[5];
    const float* wox_b = (const float*)d_in[6];
    const float* wcx_w = (const float*)d_in[7];
    const float* wcx_b = (const float*)d_in[8];
    const float* tfy_w = (const float*)d_in[9];
    const float* tiy_w = (const float*)d_in[10];
    const float* toy_w = (const float*)d_in[11];
    const float* tcy_w = (const float*)d_in[12];
    const float* wym_w = (const float*)d_in[13];
    float* out = (float*)d_out;

    gemm_input<<<dim3(R_ / 128, 16000 / 128), 256>>>(
        x, wfx_w, wix_w, wox_w, wcx_w, wfx_b, wix_b, wox_b, wcx_b);

    gemm_comb<<<dim3(R_ / 128, H_ / 128), 256>>>(
        wym_w, tfy_w, tiy_w, toy_w, tcy_w);

    cudaFuncSetAttribute(lstm_rec, cudaFuncAttributeMaxDynamicSharedMemorySize, SM_TOT);
    lstm_rec<<<NBLK, 256, SM_TOT>>>(out);
}

// round 10
// speedup vs baseline: 2.3707x; 1.0812x over previous
#include <cuda_runtime.h>
#include <math.h>

typedef unsigned long long u64;
typedef unsigned int u32;

#define T_   1000
#define B_   16
#define I_   440
#define H_   1024
#define P_   512
#define R_   4096   // 4*H, column-interleaved: col = hh*4 + gate (f,i,o,c)
#define NBLK 128

// ---------------- device scratch (no runtime allocation allowed) ----------------
static __device__ float g_G[(size_t)T_ * B_ * R_];  // 262 MB: input projections [t][b][col]
// A-fragment array for mma: [block][warp][kt][mt][term(hi/lo)][lane*4+r] (u32 bf16x2)
static __device__ u32   g_Af[(size_t)NBLK * 8 * 8 * 2 * 2 * 128];   // 16 MB
static __device__ float g_h[2][H_ * B_];            // double-buffered hidden [buf][k][b]
static __device__ unsigned g_count = 0;             // barrier arrivals (self-resetting)
static __device__ unsigned g_gen   = 0;             // barrier generation (monotonic)

// ---------------- helpers ----------------
__device__ __forceinline__ u64 pack2(float lo, float hi) {
    u64 r; asm("mov.b64 %0, {%1, %2};" : "=l"(r) : "f"(lo), "f"(hi)); return r;
}
__device__ __forceinline__ void unpack2(u64 v, float& lo, float& hi) {
    asm("mov.b64 {%0, %1}, %2;" : "=f"(lo), "=f"(hi) : "l"(v));
}
__device__ __forceinline__ u64 fadd2(u64 a, u64 b) {
    u64 d; asm("add.rn.f32x2 %0, %1, %2;" : "=l"(d) : "l"(a), "l"(b)); return d;
}

// pack two f32 into bf16x2: low 16 bits = first arg, high 16 bits = second arg
__device__ __forceinline__ u32 bf16x2_of(float lo_elem, float hi_elem) {
    u32 d; asm("cvt.rn.bf16x2.f32 %0, %1, %2;" : "=r"(d) : "f"(hi_elem), "f"(lo_elem));
    return d;
}

// mma.sync m16n8k16 bf16 -> f32 accum (row.col)
#define MMA_BF16(d, a, b) \
    asm volatile( \
        "mma.sync.aligned.m16n8k16.row.col.f32.bf16.bf16.f32 " \
        "{%0,%1,%2,%3}, {%4,%5,%6,%7}, {%8,%9}, {%0,%1,%2,%3};\n" \
        : "+f"((d)[0]), "+f"((d)[1]), "+f"((d)[2]), "+f"((d)[3]) \
        : "r"((a)[0]), "r"((a)[1]), "r"((a)[2]), "r"((a)[3]), \
          "r"((b)[0]), "r"((b)[1]))

// ---------------- grid barrier: scoped release/acquire, NO membar (no CCTL.IVALL) ----
__device__ __forceinline__ void gsync(unsigned target) {
    __syncthreads();
    if (threadIdx.x == 0) {
        unsigned old;
        asm volatile("atom.add.release.gpu.u32 %0, [%1], %2;"
                     : "=r"(old) : "l"(&g_count), "r"(1u) : "memory");
        if (old == NBLK - 1) {
            asm volatile("st.relaxed.gpu.u32 [%0], %1;" :: "l"(&g_count), "r"(0u) : "memory");
            asm volatile("st.release.gpu.u32 [%0], %1;" :: "l"(&g_gen), "r"(target) : "memory");
        } else {
            unsigned cur;
            do {
                asm volatile("ld.acquire.gpu.u32 %0, [%1];"
                             : "=r"(cur) : "l"(&g_gen) : "memory");
            } while ((int)(cur - target) < 0);
        }
    }
    __syncthreads();
}

// =====================================================================
// Kernel 1 (tensor cores): G[m][col] = X @ Wcat^T + bias
//   split-bf16 3-term mma, m16n8k16: A = X rows (m), B = W cols (n).
//   Block 128m x 64col, 8 warps (4 m-groups x 2 col-groups),
//   warp 32m x 32col = 2mt x 4nt tiles. K = 440 padded to 28 k-steps.
//   fp32 tiles staged to smem pre-split into bf16x2 hi/lo packs
//   ([row][kpair], stride 9 u32 -> near-conflict-free LDS.32 frag gathers).
// =====================================================================
__global__ __launch_bounds__(256) void gemm_input_tc(
    const float* __restrict__ X,
    const float* __restrict__ wf, const float* __restrict__ wi,
    const float* __restrict__ wo, const float* __restrict__ wc,
    const float* __restrict__ bf, const float* __restrict__ bi,
    const float* __restrict__ bo, const float* __restrict__ bc)
{
    __shared__ u32 Xhi[128 * 9], Xlo[128 * 9];   // [row][kpair0..7], stride 9
    __shared__ u32 Whi[64 * 9],  Wlo[64 * 9];

    const int tid  = threadIdx.x;
    const int lane = tid & 31;
    const int wid  = tid >> 5;
    const int wm   = wid >> 1;        // m-group 0..3 (32 rows)
    const int wcg  = wid & 1;         // col-group 0..1 (32 cols)

    const int c0 = blockIdx.x * 64;   // cols (interleaved)
    const int m0 = blockIdx.y * 128;  // rows (t*16+b)

    const int l4  = lane >> 2;        // l/4
    const int lm  = lane & 3;         // l%4

    const float* wsel[4] = {wf, wi, wo, wc};
    const float* bsel[4] = {bf, bi, bo, bc};

    // X staging assignment: 512 float4 (128 rows x 4) over 256 thr = 2 each
    const int xr0 = tid >> 2;               // row for idx = tid     (0..63)
    const int xr1 = (tid + 256) >> 2;       // row for idx = tid+256 (64..127)
    const int xj  = tid & 3;                // k-quad 0..3 (same for both)
    // W staging: 256 float4 (64 rows x 4) = 1 each
    const int wr  = tid >> 2;               // col-row 0..63
    const int wj  = tid & 3;
    const int wcol = c0 + wr;
    const float* Wrow = wsel[wcol & 3] + (size_t)(wcol >> 2) * I_;

    // per-lane bias for owned cols (same across mt / rows)
    float bias0[4], bias1[4];
#pragma unroll
    for (int nt = 0; nt < 4; ++nt) {
        int c = c0 + wcg * 32 + nt * 8 + lm * 2;
        bias0[nt] = bsel[c & 3][c >> 2];
        bias1[nt] = bsel[(c + 1) & 3][(c + 1) >> 2];
    }

    float d[2][4][4];
#pragma unroll
    for (int mt = 0; mt < 2; ++mt)
#pragma unroll
        for (int nt = 0; nt < 4; ++nt)
#pragma unroll
            for (int q = 0; q < 4; ++q) d[mt][nt][q] = 0.f;

    // prefetch k-step 0
    float4 xv0, xv1, wv;
    {
        const int k = 0 + 4 * xj;
        xv0 = (k < I_) ? *(const float4*)(X + (size_t)(m0 + xr0) * I_ + k)
                       : make_float4(0, 0, 0, 0);
        xv1 = (k < I_) ? *(const float4*)(X + (size_t)(m0 + xr1) * I_ + k)
                       : make_float4(0, 0, 0, 0);
        wv  = (k < I_) ? *(const float4*)(Wrow + k) : make_float4(0, 0, 0, 0);
    }

    for (int ks = 0; ks < 28; ++ks) {
        // ---- convert prefetched fp32 -> split bf16 packs in smem ----
        {
            // X row xr0
            u32 hA = bf16x2_of(xv0.x, xv0.y), hB = bf16x2_of(xv0.z, xv0.w);
            u32 lA = bf16x2_of(xv0.x - __uint_as_float(hA << 16),
                               xv0.y - __uint_as_float(hA & 0xFFFF0000u));
            u32 lB = bf16x2_of(xv0.z - __uint_as_float(hB << 16),
                               xv0.w - __uint_as_float(hB & 0xFFFF0000u));
            Xhi[xr0 * 9 + 2 * xj] = hA; Xhi[xr0 * 9 + 2 * xj + 1] = hB;
            Xlo[xr0 * 9 + 2 * xj] = lA; Xlo[xr0 * 9 + 2 * xj + 1] = lB;
            // X row xr1
            hA = bf16x2_of(xv1.x, xv1.y); hB = bf16x2_of(xv1.z, xv1.w);
            lA = bf16x2_of(xv1.x - __uint_as_float(hA << 16),
                           xv1.y - __uint_as_float(hA & 0xFFFF0000u));
            lB = bf16x2_of(xv1.z - __uint_as_float(hB << 16),
                           xv1.w - __uint_as_float(hB & 0xFFFF0000u));
            Xhi[xr1 * 9 + 2 * xj] = hA; Xhi[xr1 * 9 + 2 * xj + 1] = hB;
            Xlo[xr1 * 9 + 2 * xj] = lA; Xlo[xr1 * 9 + 2 * xj + 1] = lB;
            // W
            hA = bf16x2_of(wv.x, wv.y); hB = bf16x2_of(wv.z, wv.w);
            lA = bf16x2_of(wv.x - __uint_as_float(hA << 16),
                           wv.y - __uint_as_float(hA & 0xFFFF0000u));
            lB = bf16x2_of(wv.z - __uint_as_float(hB << 16),
                           wv.w - __uint_as_float(hB & 0xFFFF0000u));
            Whi[wr * 9 + 2 * wj] = hA; Whi[wr * 9 + 2 * wj + 1] = hB;
            Wlo[wr * 9 + 2 * wj] = lA; Wlo[wr * 9 + 2 * wj + 1] = lB;
        }
        __syncthreads();

        // ---- prefetch next k-step ----
        if (ks + 1 < 28) {
            const int k = (ks + 1) * 16 + 4 * xj;
            xv0 = (k < I_) ? *(const float4*)(X + (size_t)(m0 + xr0) * I_ + k)
                           : make_float4(0, 0, 0, 0);
            xv1 = (k < I_) ? *(const float4*)(X + (size_t)(m0 + xr1) * I_ + k)
                           : make_float4(0, 0, 0, 0);
            wv  = (k < I_) ? *(const float4*)(Wrow + k) : make_float4(0, 0, 0, 0);
        }

        // ---- fragment loads + mma ----
        u32 ahi[2][4], alo[2][4];
#pragma unroll
        for (int mt = 0; mt < 2; ++mt)
#pragma unroll
            for (int r = 0; r < 4; ++r) {
                int row = wm * 32 + mt * 16 + l4 + 8 * (r & 1);
                int kp  = lm + 4 * (r >> 1);
                ahi[mt][r] = Xhi[row * 9 + kp];
                alo[mt][r] = Xlo[row * 9 + kp];
            }
#pragma unroll
        for (int nt = 0; nt < 4; ++nt) {
            u32 bhi[2], blo[2];
            int n = wcg * 32 + nt * 8 + l4;
            bhi[0] = Whi[n * 9 + lm];     bhi[1] = Whi[n * 9 + lm + 4];
            blo[0] = Wlo[n * 9 + lm];     blo[1] = Wlo[n * 9 + lm + 4];
#pragma unroll
            for (int mt = 0; mt < 2; ++mt) {
                MMA_BF16(d[mt][nt], ahi[mt], bhi);
                MMA_BF16(d[mt][nt], ahi[mt], blo);
                MMA_BF16(d[mt][nt], alo[mt], bhi);
            }
        }
        __syncthreads();
    }

    // ---- epilogue: bias + float2 stores to G[m][col] ----
#pragma unroll
    for (int mt = 0; mt < 2; ++mt) {
        const int row = m0 + wm * 32 + mt * 16 + l4;
#pragma unroll
        for (int nt = 0; nt < 4; ++nt) {
            const int col = c0 + wcg * 32 + nt * 8 + lm * 2;
            *(float2*)(g_G + (size_t)row * R_ + col) =
                make_float2(d[mt][nt][0] + bias0[nt], d[mt][nt][1] + bias1[nt]);
            *(float2*)(g_G + (size_t)(row + 8) * R_ + col) =
                make_float2(d[mt][nt][2] + bias0[nt], d[mt][nt][3] + bias1[nt]);
        }
    }
}

// =====================================================================
// Kernel 2: M[col][k] = sum_p wym[p][k] * Wr_gate(col)[hh(col)][p],
//   emitted as split-bf16 (hi+lo) mma A-FRAGMENTS (unchanged from R8).
// =====================================================================
__global__ __launch_bounds__(256) void gemm_comb(
    const float* __restrict__ wym,
    const float* __restrict__ tf, const float* __restrict__ ti,
    const float* __restrict__ to_, const float* __restrict__ tc)
{
    __shared__ __align__(16) float As[8][128];
    __shared__ __align__(16) float Bs[8][128];

    const int tid = threadIdx.x;
    const int n0  = blockIdx.x * 128;   // cols
    const int m0  = blockIdx.y * 128;   // k

    const int akk = tid >> 5;
    const int amm = (tid & 31) * 4;
    const float* aptr = wym + (size_t)akk * H_ + m0 + amm;

    const int lr = tid >> 1;
    const int lc = (tid & 1) * 4;
    const int bgate = lr & 3;
    const float* Wr = (bgate == 0) ? tf : (bgate == 1) ? ti : (bgate == 2) ? to_ : tc;
    const float* bptr = Wr + (size_t)((n0 >> 2) + (lr >> 2)) * P_ + lc;

    float4 areg = *(const float4*)aptr;
    float4 breg = *(const float4*)bptr;

    const int tm = (tid >> 4) * 8;
    const int tn = (tid & 15) * 8;

    float acc[8][8];
#pragma unroll
    for (int i = 0; i < 8; ++i)
#pragma unroll
        for (int j = 0; j < 8; ++j) acc[i][j] = 0.f;

    for (int k0 = 0; k0 < P_; k0 += 8) {
        *(float4*)&As[akk][amm] = areg;
        Bs[lc + 0][lr] = breg.x; Bs[lc + 1][lr] = breg.y;
        Bs[lc + 2][lr] = breg.z; Bs[lc + 3][lr] = breg.w;
        __syncthreads();
        if (k0 + 8 < P_) {
            areg = *(const float4*)(aptr + (size_t)(k0 + 8) * H_);
            breg = *(const float4*)(bptr + k0 + 8);
        }
#pragma unroll
        for (int kk = 0; kk < 8; ++kk) {
            float a[8], b[8];
            *(float4*)(a)     = *(const float4*)&As[kk][tm];
            *(float4*)(a + 4) = *(const float4*)&As[kk][tm + 4];
            *(float4*)(b)     = *(const float4*)&Bs[kk][tn];
            *(float4*)(b + 4) = *(const float4*)&Bs[kk][tn + 4];
#pragma unroll
            for (int i = 0; i < 8; ++i)
#pragma unroll
                for (int j = 0; j < 8; ++j)
                    acc[i][j] = fmaf(a[i], b[j], acc[i][j]);
        }
        __syncthreads();
    }

#pragma unroll
    for (int i = 0; i < 8; i += 2) {
        const int k = m0 + tm + i;
#pragma unroll
        for (int j = 0; j < 8; ++j) {
            const int col = n0 + tn + j;
            float v0 = acc[i][j], v1 = acc[i + 1][j];
            u32 hi = bf16x2_of(v0, v1);
            float h0 = __uint_as_float(hi << 16);
            float h1 = __uint_as_float(hi & 0xFFFF0000u);
            u32 lo = bf16x2_of(v0 - h0, v1 - h1);
            const int blk  = col >> 5;
            const int warp = k >> 7;
            const int kt   = (k >> 4) & 7;
            const int mt   = (col >> 4) & 1;
            const int r    = ((col >> 3) & 1) | (((k >> 3) & 1) << 1);
            const int lane = ((col & 7) << 2) | ((k & 7) >> 1);
            size_t base = ((((size_t)(blk * 8 + warp) * 8 + kt) * 2 + mt) * 2) * 128;
            g_Af[base + lane * 4 + r]       = hi;
            g_Af[base + 128 + lane * 4 + r] = lo;
        }
    }
}

// =====================================================================
// Kernel 3: persistent recurrence, tensor-core matmul (unchanged from R8).
// =====================================================================
__device__ __forceinline__ float sigmoidf_(float x) { return 1.f / (1.f + __expf(-x)); }

#define SM_PART 81920
#define SM_GSM  102400
#define SM_TOT  104704

__global__ __launch_bounds__(256, 1) void lstm_rec(float* __restrict__ out)
{
    extern __shared__ __align__(16) char smem[];
    float* h_s  = (float*)smem;
    float* part = (float*)(smem + SM_PART);
    float* gsm  = (float*)(smem + SM_GSM);

    const int tid  = threadIdx.x;
    const int bid  = blockIdx.x;
    const int wid  = tid >> 5;
    const int lane = tid & 31;

    unsigned base = 0;
    if (tid == 0)
        asm volatile("ld.relaxed.gpu.u32 %0, [%1];" : "=r"(base) : "l"(&g_gen) : "memory");

    {
        int i = bid * 256 + tid;
        __stcg(&((float*)g_h)[i], 0.f);
    }
    gsync(base + 1);

    const int hh0 = bid * 8;
    const int pb  = tid >> 3;
    const int phl = tid & 7;
    float cstate = 0.f;

    const u32* Afbase = g_Af + ((size_t)(bid * 8 + wid) * 8) * 2 * 2 * 128;
    const float* Gbase = g_G + (size_t)pb * R_ + (size_t)(hh0 + phl) * 4;

    const int ln4  = lane >> 2;
    const int lm4  = lane & 3;

    for (int t = 0; t < T_; ++t) {
        float4 gg;
        if (tid < 128)
            gg = __ldcs((const float4*)(Gbase + (size_t)t * B_ * R_));

        {
            const float4* src = (const float4*)(&g_h[t & 1][0]);
#pragma unroll
            for (int i = 0; i < 16; ++i) {
                int idx = wid * 512 + i * 32 + lane;
                int k  = idx >> 2, bq = idx & 3;
                float4 v = __ldcg(src + idx);
                *(float4*)&h_s[k * 20 + bq * 4] = v;
            }
            __syncwarp();
        }

        float d[2][2][4];
#pragma unroll
        for (int mt = 0; mt < 2; ++mt)
#pragma unroll
            for (int nt = 0; nt < 2; ++nt)
#pragma unroll
                for (int q = 0; q < 4; ++q) d[mt][nt][q] = 0.f;

#pragma unroll
        for (int kt = 0; kt < 8; ++kt) {
            u32 ahi[2][4], alo[2][4];
#pragma unroll
            for (int mt = 0; mt < 2; ++mt) {
                const u32* p = Afbase + ((size_t)(kt * 2 + mt) * 2) * 128 + lane * 4;
                *(uint4*)ahi[mt] = *(const uint4*)p;
                *(uint4*)alo[mt] = *(const uint4*)(p + 128);
            }
            u32 bhi[2][2], blo[2][2];
            const int kb = wid * 128 + kt * 16 + lm4 * 2;
#pragma unroll
            for (int nt = 0; nt < 2; ++nt) {
                const int n = nt * 8 + ln4;
                float f0 = h_s[(kb + 0) * 20 + n];
                float f1 = h_s[(kb + 1) * 20 + n];
                float f2 = h_s[(kb + 8) * 20 + n];
                float f3 = h_s[(kb + 9) * 20 + n];
                u32 p0 = bf16x2_of(f0, f1);
                u32 p1 = bf16x2_of(f2, f3);
                float e0 = f0 - __uint_as_float(p0 << 16);
                float e1 = f1 - __uint_as_float(p0 & 0xFFFF0000u);
                float e2 = f2 - __uint_as_float(p1 << 16);
                float e3 = f3 - __uint_as_float(p1 & 0xFFFF0000u);
                bhi[nt][0] = p0; bhi[nt][1] = p1;
                blo[nt][0] = bf16x2_of(e0, e1);
                blo[nt][1] = bf16x2_of(e2, e3);
            }
#pragma unroll
            for (int mt = 0; mt < 2; ++mt)
#pragma unroll
                for (int nt = 0; nt < 2; ++nt) {
                    MMA_BF16(d[mt][nt], ahi[mt], bhi[nt]);
                    MMA_BF16(d[mt][nt], ahi[mt], blo[nt]);
                    MMA_BF16(d[mt][nt], alo[mt], bhi[nt]);
                }
        }

#pragma unroll
        for (int mt = 0; mt < 2; ++mt)
#pragma unroll
            for (int nt = 0; nt < 2; ++nt) {
                const int c0 = mt * 16 + ln4;
                const int b  = nt * 8 + lm4 * 2;
                *(float2*)&part[(wid * 32 + c0) * 20 + b] =
                    make_float2(d[mt][nt][0], d[mt][nt][1]);
                *(float2*)&part[(wid * 32 + c0 + 8) * 20 + b] =
                    make_float2(d[mt][nt][2], d[mt][nt][3]);
            }
        __syncthreads();

        {
            const int ri = tid >> 3;
            const int bp = tid & 7;
            u64 s = *(const u64*)&part[(ri) * 20 + 2 * bp];
#pragma unroll
            for (int w = 1; w < 8; ++w)
                s = fadd2(s, *(const u64*)&part[(w * 32 + ri) * 20 + 2 * bp]);
            float lo, hi;
            unpack2(s, lo, hi);
            gsm[(2 * bp) * 36 + ri]     = lo;
            gsm[(2 * bp + 1) * 36 + ri] = hi;
        }
        __syncthreads();

        if (tid < 128) {
            float4 gd = *(const float4*)&gsm[pb * 36 + phl * 4];
            float zf = gg.x + gd.x;
            float zi = gg.y + gd.y;
            float zo = gg.z + gd.z;
            float zc = gg.w + gd.w;
            float ft = sigmoidf_(zf);
            float it = sigmoidf_(zi);
            float ot = sigmoidf_(zo);
            cstate = it * tanhf(zc) + ft * cstate;
            float h = ot * tanhf(cstate);
            __stcg(&g_h[(t + 1) & 1][(hh0 + phl) * 16 + pb], h);
            __stcs(&out[((size_t)(t * B_ + pb) << 10) + hh0 + phl], h);
            if (t + 1 < T_) {
                const float* np = Gbase + (size_t)(t + 1) * B_ * R_;
                asm volatile("prefetch.global.L2 [%0];" :: "l"(np));
            }
        }

        gsync(base + 2 + t);
    }
}

// =====================================================================
// launch
// =====================================================================
extern "C" void kernel_launch(void* const* d_in, const int* in_sizes, int n_in,
                              void* d_out, int out_size)
{
    const float* x     = (const float*)d_in[0];
    const float* wfx_w = (const float*)d_in[1];
    const float* wfx_b = (const float*)d_in[2];
    const float* wix_w = (const float*)d_in[3];
    const float* wix_b = (const float*)d_in[4];
    const float* wox_w = (const float*)d_in[5];
    const float* wox_b = (const float*)d_in[6];
    const float* wcx_w = (const float*)d_in[7];
    const float* wcx_b = (const float*)d_in[8];
    const float* tfy_w = (const float*)d_in[9];
    const float* tiy_w = (const float*)d_in[10];
    const float* toy_w = (const float*)d_in[11];
    const float* tcy_w = (const float*)d_in[12];
    const float* wym_w = (const float*)d_in[13];
    float* out = (float*)d_out;

    // G = x @ Wx^T + b via split-bf16 tensor cores
    gemm_input_tc<<<dim3(R_ / 64, 16000 / 128), 256>>>(
        x, wfx_w, wix_w, wox_w, wcx_w, wfx_b, wix_b, wox_b, wcx_b);

    // M fragments for the recurrence
    gemm_comb<<<dim3(R_ / 128, H_ / 128), 256>>>(
        wym_w, tfy_w, tiy_w, toy_w, tcy_w);

    cudaFuncSetAttribute(lstm_rec, cudaFuncAttributeMaxDynamicSharedMemorySize, SM_TOT);
    lstm_rec<<<NBLK, 256, SM_TOT>>>(out);
}

// round 14
// speedup vs baseline: 2.5365x; 1.0699x over previous
#include <cuda_runtime.h>
#include <math.h>

typedef unsigned long long u64;
typedef unsigned int u32;

#define T_   1000
#define B_   16
#define I_   440
#define H_   1024
#define P_   512
#define R_   4096   // 4*H, column-interleaved: col = hh*4 + gate (f,i,o,c)
#define NBLK 128

// smem row stride for frag arrays, in u32. MUST keep row starts 16B-aligned
// for ldmatrix (stride*4 % 16 == 0). 12 -> 48B: aligned + conflict-free phases.
#define FS 12

// ---------------- device scratch (no runtime allocation allowed) ----------------
static __device__ float g_G[(size_t)T_ * B_ * R_];  // 262 MB: input projections [t][b][col]
// A-fragment array for mma: [block][warp][kt][mt][term(hi/lo)][lane*4+r] (u32 bf16x2)
static __device__ u32   g_Af[(size_t)NBLK * 8 * 8 * 2 * 2 * 128];   // 16 MB
static __device__ float g_h[2][H_ * B_];            // double-buffered hidden [buf][k][b]
static __device__ unsigned g_count = 0;             // barrier arrivals (self-resetting)
static __device__ unsigned g_gen   = 0;             // barrier generation (monotonic)

// ---------------- helpers ----------------
__device__ __forceinline__ u64 pack2(float lo, float hi) {
    u64 r; asm("mov.b64 %0, {%1, %2};" : "=l"(r) : "f"(lo), "f"(hi)); return r;
}
__device__ __forceinline__ void unpack2(u64 v, float& lo, float& hi) {
    asm("mov.b64 {%0, %1}, %2;" : "=f"(lo), "=f"(hi) : "l"(v));
}
__device__ __forceinline__ u64 fadd2(u64 a, u64 b) {
    u64 d; asm("add.rn.f32x2 %0, %1, %2;" : "=l"(d) : "l"(a), "l"(b)); return d;
}

// pack two f32 into bf16x2: low 16 bits = first arg, high 16 bits = second arg
__device__ __forceinline__ u32 bf16x2_of(float lo_elem, float hi_elem) {
    u32 d; asm("cvt.rn.bf16x2.f32 %0, %1, %2;" : "=r"(d) : "f"(hi_elem), "f"(lo_elem));
    return d;
}

__device__ __forceinline__ float tanh_ap(float x) {
    float y; asm("tanh.approx.f32 %0, %1;" : "=f"(y) : "f"(x)); return y;
}
__device__ __forceinline__ float sigmoid_ap(float x) {
    return 0.5f * tanh_ap(0.5f * x) + 0.5f;
}

// mma.sync m16n8k16 bf16 -> f32 accum (row.col)
#define MMA_BF16(d, a, b) \
    asm volatile( \
        "mma.sync.aligned.m16n8k16.row.col.f32.bf16.bf16.f32 " \
        "{%0,%1,%2,%3}, {%4,%5,%6,%7}, {%8,%9}, {%0,%1,%2,%3};\n" \
        : "+f"((d)[0]), "+f"((d)[1]), "+f"((d)[2]), "+f"((d)[3]) \
        : "r"((a)[0]), "r"((a)[1]), "r"((a)[2]), "r"((a)[3]), \
          "r"((b)[0]), "r"((b)[1]))

__device__ __forceinline__ void ldsm_x4(u32& r0, u32& r1, u32& r2, u32& r3, u32 addr) {
    asm volatile("ldmatrix.sync.aligned.m8n8.x4.shared.b16 {%0,%1,%2,%3}, [%4];"
                 : "=r"(r0), "=r"(r1), "=r"(r2), "=r"(r3) : "r"(addr));
}
__device__ __forceinline__ void ldsm_x2(u32& r0, u32& r1, u32 addr) {
    asm volatile("ldmatrix.sync.aligned.m8n8.x2.shared.b16 {%0,%1}, [%2];"
                 : "=r"(r0), "=r"(r1) : "r"(addr));
}

// ---------------- grid barrier: scoped release/acquire, NO membar (no CCTL.IVALL) ----
__device__ __forceinline__ void gsync(unsigned target) {
    __syncthreads();
    if (threadIdx.x == 0) {
        unsigned old;
        asm volatile("atom.add.release.gpu.u32 %0, [%1], %2;"
                     : "=r"(old) : "l"(&g_count), "r"(1u) : "memory");
        if (old == NBLK - 1) {
            asm volatile("st.relaxed.gpu.u32 [%0], %1;" :: "l"(&g_count), "r"(0u) : "memory");
            asm volatile("st.release.gpu.u32 [%0], %1;" :: "l"(&g_gen), "r"(target) : "memory");
        } else {
            unsigned cur;
            do {
                asm volatile("ld.acquire.gpu.u32 %0, [%1];"
                             : "=r"(cur) : "l"(&g_gen) : "memory");
            } while ((int)(cur - target) < 0);
        }
    }
    __syncthreads();
}

// ---------------- dummy kernel: shifts ncu's captured launch (-s 5) onto lstm_rec ----
__global__ void dummy_k() {}

// =====================================================================
// Kernel 1 (tensor cores + ldmatrix): G[m][col] = X @ Wcat^T + bias
//   split-bf16 3-term mma, m16n8k16. Block 128m x 64col, 8 warps.
//   Frag gathers via ldmatrix (12 LDSM vs 64 LDS.32 per warp/k-step).
//   Row stride FS=12 u32 (48B): 16B-aligned rows, conflict-free phases.
// =====================================================================
__global__ __launch_bounds__(256) void gemm_input_tc(
    const float* __restrict__ X,
    const float* __restrict__ wf, const float* __restrict__ wi,
    const float* __restrict__ wo, const float* __restrict__ wc,
    const float* __restrict__ bf, const float* __restrict__ bi,
    const float* __restrict__ bo, const float* __restrict__ bc)
{
    __shared__ __align__(16) u32 Xhi[128 * FS], Xlo[128 * FS];  // [row][kpair0..7]
    __shared__ __align__(16) u32 Whi[64 * FS],  Wlo[64 * FS];

    const int tid  = threadIdx.x;
    const int lane = tid & 31;
    const int wid  = tid >> 5;
    const int wm   = wid >> 1;        // m-group 0..3 (32 rows)
    const int wcg  = wid & 1;         // col-group 0..1 (32 cols)

    const int c0 = blockIdx.x * 64;   // cols (interleaved)
    const int m0 = blockIdx.y * 128;  // rows (t*16+b)

    const int lm  = lane & 3;         // l%4

    const float* wsel[4] = {wf, wi, wo, wc};
    const float* bsel[4] = {bf, bi, bo, bc};

    // X staging: 512 float4 over 256 thr = 2 each
    const int xr0 = tid >> 2;
    const int xr1 = (tid + 256) >> 2;
    const int xj  = tid & 3;
    // W staging: 256 float4 = 1 each
    const int wr  = tid >> 2;
    const int wj  = tid & 3;
    const int wcol = c0 + wr;
    const float* Wrow = wsel[wcol & 3] + (size_t)(wcol >> 2) * I_;

    // ldmatrix per-lane addresses (byte offsets)
    // A x4 reg order r: [rows+0,k0-7],[rows+8,k0-7],[rows+0,k8-15],[rows+8,k8-15]
    //   lane j -> row (j&7) + 8*((j>>3)&1), k-half (j>>4)
    const u32 xhiB = (u32)__cvta_generic_to_shared(Xhi);
    const u32 xloB = (u32)__cvta_generic_to_shared(Xlo);
    const u32 whiB = (u32)__cvta_generic_to_shared(Whi);
    const u32 wloB = (u32)__cvta_generic_to_shared(Wlo);
    const int arow = wm * 32 + (lane & 7) + 8 * ((lane >> 3) & 1);
    const u32 aoff = (u32)((arow * FS + 4 * (lane >> 4)) * 4);    // mt=0; mt=1 adds 16*FS*4
    const int bl   = lane & 15;                                    // x2 uses lanes 0-15
    const u32 boff = (u32)(((wcg * 32 + (bl & 7)) * FS + 4 * (bl >> 3)) * 4);

    // per-lane bias for owned cols
    float bias0[4], bias1[4];
#pragma unroll
    for (int nt = 0; nt < 4; ++nt) {
        int c = c0 + wcg * 32 + nt * 8 + lm * 2;
        bias0[nt] = bsel[c & 3][c >> 2];
        bias1[nt] = bsel[(c + 1) & 3][(c + 1) >> 2];
    }

    float d[2][4][4];
#pragma unroll
    for (int mt = 0; mt < 2; ++mt)
#pragma unroll
        for (int nt = 0; nt < 4; ++nt)
#pragma unroll
            for (int q = 0; q < 4; ++q) d[mt][nt][q] = 0.f;

    // prefetch k-step 0
    float4 xv0, xv1, wv;
    {
        const int k = 0 + 4 * xj;
        xv0 = (k < I_) ? *(const float4*)(X + (size_t)(m0 + xr0) * I_ + k)
                       : make_float4(0, 0, 0, 0);
        xv1 = (k < I_) ? *(const float4*)(X + (size_t)(m0 + xr1) * I_ + k)
                       : make_float4(0, 0, 0, 0);
        wv  = (k < I_) ? *(const float4*)(Wrow + k) : make_float4(0, 0, 0, 0);
    }

    for (int ks = 0; ks < 28; ++ks) {
        // ---- convert prefetched fp32 -> split bf16 packs in smem ----
        {
            u32 hA = bf16x2_of(xv0.x, xv0.y), hB = bf16x2_of(xv0.z, xv0.w);
            u32 lA = bf16x2_of(xv0.x - __uint_as_float(hA << 16),
                               xv0.y - __uint_as_float(hA & 0xFFFF0000u));
            u32 lB = bf16x2_of(xv0.z - __uint_as_float(hB << 16),
                               xv0.w - __uint_as_float(hB & 0xFFFF0000u));
            Xhi[xr0 * FS + 2 * xj] = hA; Xhi[xr0 * FS + 2 * xj + 1] = hB;
            Xlo[xr0 * FS + 2 * xj] = lA; Xlo[xr0 * FS + 2 * xj + 1] = lB;
            hA = bf16x2_of(xv1.x, xv1.y); hB = bf16x2_of(xv1.z, xv1.w);
            lA = bf16x2_of(xv1.x - __uint_as_float(hA << 16),
                           xv1.y - __uint_as_float(hA & 0xFFFF0000u));
            lB = bf16x2_of(xv1.z - __uint_as_float(hB << 16),
                           xv1.w - __uint_as_float(hB & 0xFFFF0000u));
            Xhi[xr1 * FS + 2 * xj] = hA; Xhi[xr1 * FS + 2 * xj + 1] = hB;
            Xlo[xr1 * FS + 2 * xj] = lA; Xlo[xr1 * FS + 2 * xj + 1] = lB;
            hA = bf16x2_of(wv.x, wv.y); hB = bf16x2_of(wv.z, wv.w);
            lA = bf16x2_of(wv.x - __uint_as_float(hA << 16),
                           wv.y - __uint_as_float(hA & 0xFFFF0000u));
            lB = bf16x2_of(wv.z - __uint_as_float(hB << 16),
                           wv.w - __uint_as_float(hB & 0xFFFF0000u));
            Whi[wr * FS + 2 * wj] = hA; Whi[wr * FS + 2 * wj + 1] = hB;
            Wlo[wr * FS + 2 * wj] = lA; Wlo[wr * FS + 2 * wj + 1] = lB;
        }
        __syncthreads();

        // ---- prefetch next k-step ----
        if (ks + 1 < 28) {
            const int k = (ks + 1) * 16 + 4 * xj;
            xv0 = (k < I_) ? *(const float4*)(X + (size_t)(m0 + xr0) * I_ + k)
                           : make_float4(0, 0, 0, 0);
            xv1 = (k < I_) ? *(const float4*)(X + (size_t)(m0 + xr1) * I_ + k)
                           : make_float4(0, 0, 0, 0);
            wv  = (k < I_) ? *(const float4*)(Wrow + k) : make_float4(0, 0, 0, 0);
        }

        // ---- fragment loads via ldmatrix + mma ----
        u32 ahi[2][4], alo[2][4];
        ldsm_x4(ahi[0][0], ahi[0][1], ahi[0][2], ahi[0][3], xhiB + aoff);
        ldsm_x4(ahi[1][0], ahi[1][1], ahi[1][2], ahi[1][3], xhiB + aoff + 16 * FS * 4);
        ldsm_x4(alo[0][0], alo[0][1], alo[0][2], alo[0][3], xloB + aoff);
        ldsm_x4(alo[1][0], alo[1][1], alo[1][2], alo[1][3], xloB + aoff + 16 * FS * 4);
#pragma unroll
        for (int nt = 0; nt < 4; ++nt) {
            u32 bhi[2], blo[2];
            ldsm_x2(bhi[0], bhi[1], whiB + boff + (u32)(nt * 8 * FS * 4));
            ldsm_x2(blo[0], blo[1], wloB + boff + (u32)(nt * 8 * FS * 4));
#pragma unroll
            for (int mt = 0; mt < 2; ++mt) {
                MMA_BF16(d[mt][nt], ahi[mt], bhi);
                MMA_BF16(d[mt][nt], ahi[mt], blo);
                MMA_BF16(d[mt][nt], alo[mt], bhi);
            }
        }
        __syncthreads();
    }

    // ---- epilogue: bias + float2 stores to G[m][col] ----
    const int l4 = lane >> 2;
#pragma unroll
    for (int mt = 0; mt < 2; ++mt) {
        const int row = m0 + wm * 32 + mt * 16 + l4;
#pragma unroll
        for (int nt = 0; nt < 4; ++nt) {
            const int col = c0 + wcg * 32 + nt * 8 + lm * 2;
            *(float2*)(g_G + (size_t)row * R_ + col) =
                make_float2(d[mt][nt][0] + bias0[nt], d[mt][nt][1] + bias1[nt]);
            *(float2*)(g_G + (size_t)(row + 8) * R_ + col) =
                make_float2(d[mt][nt][2] + bias0[nt], d[mt][nt][3] + bias1[nt]);
        }
    }
}

// =====================================================================
// Kernel 2: M[col][k] fragments (unchanged from R8/R10).
// =====================================================================
__global__ __launch_bounds__(256) void gemm_comb(
    const float* __restrict__ wym,
    const float* __restrict__ tf, const float* __restrict__ ti,
    const float* __restrict__ to_, const float* __restrict__ tc)
{
    __shared__ __align__(16) float As[8][128];
    __shared__ __align__(16) float Bs[8][128];

    const int tid = threadIdx.x;
    const int n0  = blockIdx.x * 128;   // cols
    const int m0  = blockIdx.y * 128;   // k

    const int akk = tid >> 5;
    const int amm = (tid & 31) * 4;
    const float* aptr = wym + (size_t)akk * H_ + m0 + amm;

    const int lr = tid >> 1;
    const int lc = (tid & 1) * 4;
    const int bgate = lr & 3;
    const float* Wr = (bgate == 0) ? tf : (bgate == 1) ? ti : (bgate == 2) ? to_ : tc;
    const float* bptr = Wr + (size_t)((n0 >> 2) + (lr >> 2)) * P_ + lc;

    float4 areg = *(const float4*)aptr;
    float4 breg = *(const float4*)bptr;

    const int tm = (tid >> 4) * 8;
    const int tn = (tid & 15) * 8;

    float acc[8][8];
#pragma unroll
    for (int i = 0; i < 8; ++i)
#pragma unroll
        for (int j = 0; j < 8; ++j) acc[i][j] = 0.f;

    for (int k0 = 0; k0 < P_; k0 += 8) {
        *(float4*)&As[akk][amm] = areg;
        Bs[lc + 0][lr] = breg.x; Bs[lc + 1][lr] = breg.y;
        Bs[lc + 2][lr] = breg.z; Bs[lc + 3][lr] = breg.w;
        __syncthreads();
        if (k0 + 8 < P_) {
            areg = *(const float4*)(aptr + (size_t)(k0 + 8) * H_);
            breg = *(const float4*)(bptr + k0 + 8);
        }
#pragma unroll
        for (int kk = 0; kk < 8; ++kk) {
            float a[8], b[8];
            *(float4*)(a)     = *(const float4*)&As[kk][tm];
            *(float4*)(a + 4) = *(const float4*)&As[kk][tm + 4];
            *(float4*)(b)     = *(const float4*)&Bs[kk][tn];
            *(float4*)(b + 4) = *(const float4*)&Bs[kk][tn + 4];
#pragma unroll
            for (int i = 0; i < 8; ++i)
#pragma unroll
                for (int j = 0; j < 8; ++j)
                    acc[i][j] = fmaf(a[i], b[j], acc[i][j]);
        }
        __syncthreads();
    }

#pragma unroll
    for (int i = 0; i < 8; i += 2) {
        const int k = m0 + tm + i;
#pragma unroll
        for (int j = 0; j < 8; ++j) {
            const int col = n0 + tn + j;
            float v0 = acc[i][j], v1 = acc[i + 1][j];
            u32 hi = bf16x2_of(v0, v1);
            float h0 = __uint_as_float(hi << 16);
            float h1 = __uint_as_float(hi & 0xFFFF0000u);
            u32 lo = bf16x2_of(v0 - h0, v1 - h1);
            const int blk  = col >> 5;
            const int warp = k >> 7;
            const int kt   = (k >> 4) & 7;
            const int mt   = (col >> 4) & 1;
            const int r    = ((col >> 3) & 1) | (((k >> 3) & 1) << 1);
            const int lane = ((col & 7) << 2) | ((k & 7) >> 1);
            size_t base = ((((size_t)(blk * 8 + warp) * 8 + kt) * 2 + mt) * 2) * 128;
            g_Af[base + lane * 4 + r]       = hi;
            g_Af[base + 128 + lane * 4 + r] = lo;
        }
    }
}

// =====================================================================
// Kernel 3: persistent recurrence, tensor-core matmul (R10 + tanh.approx).
// =====================================================================
#define SM_PART 81920
#define SM_GSM  102400
#define SM_TOT  104704

__global__ __launch_bounds__(256, 1) void lstm_rec(float* __restrict__ out)
{
    extern __shared__ __align__(16) char smem[];
    float* h_s  = (float*)smem;
    float* part = (float*)(smem + SM_PART);
    float* gsm  = (float*)(smem + SM_GSM);

    const int tid  = threadIdx.x;
    const int bid  = blockIdx.x;
    const int wid  = tid >> 5;
    const int lane = tid & 31;

    unsigned base = 0;
    if (tid == 0)
        asm volatile("ld.relaxed.gpu.u32 %0, [%1];" : "=r"(base) : "l"(&g_gen) : "memory");

    {
        int i = bid * 256 + tid;
        __stcg(&((float*)g_h)[i], 0.f);
    }
    gsync(base + 1);

    const int hh0 = bid * 8;
    const int pb  = tid >> 3;
    const int phl = tid & 7;
    float cstate = 0.f;

    const u32* Afbase = g_Af + ((size_t)(bid * 8 + wid) * 8) * 2 * 2 * 128;
    const float* Gbase = g_G + (size_t)pb * R_ + (size_t)(hh0 + phl) * 4;

    const int ln4  = lane >> 2;
    const int lm4  = lane & 3;

    for (int t = 0; t < T_; ++t) {
        float4 gg;
        if (tid < 128)
            gg = __ldcs((const float4*)(Gbase + (size_t)t * B_ * R_));

        {
            const float4* src = (const float4*)(&g_h[t & 1][0]);
#pragma unroll
            for (int i = 0; i < 16; ++i) {
                int idx = wid * 512 + i * 32 + lane;
                int k  = idx >> 2, bq = idx & 3;
                float4 v = __ldcg(src + idx);
                *(float4*)&h_s[k * 20 + bq * 4] = v;
            }
            __syncwarp();
        }

        float d[2][2][4];
#pragma unroll
        for (int mt = 0; mt < 2; ++mt)
#pragma unroll
            for (int nt = 0; nt < 2; ++nt)
#pragma unroll
                for (int q = 0; q < 4; ++q) d[mt][nt][q] = 0.f;

#pragma unroll
        for (int kt = 0; kt < 8; ++kt) {
            u32 ahi[2][4], alo[2][4];
#pragma unroll
            for (int mt = 0; mt < 2; ++mt) {
                const u32* p = Afbase + ((size_t)(kt * 2 + mt) * 2) * 128 + lane * 4;
                *(uint4*)ahi[mt] = *(const uint4*)p;
                *(uint4*)alo[mt] = *(const uint4*)(p + 128);
            }
            u32 bhi[2][2], blo[2][2];
            const int kb = wid * 128 + kt * 16 + lm4 * 2;
#pragma unroll
            for (int nt = 0; nt < 2; ++nt) {
                const int n = nt * 8 + ln4;
                float f0 = h_s[(kb + 0) * 20 + n];
                float f1 = h_s[(kb + 1) * 20 + n];
                float f2 = h_s[(kb + 8) * 20 + n];
                float f3 = h_s[(kb + 9) * 20 + n];
                u32 p0 = bf16x2_of(f0, f1);
                u32 p1 = bf16x2_of(f2, f3);
                float e0 = f0 - __uint_as_float(p0 << 16);
                float e1 = f1 - __uint_as_float(p0 & 0xFFFF0000u);
                float e2 = f2 - __uint_as_float(p1 << 16);
                float e3 = f3 - __uint_as_float(p1 & 0xFFFF0000u);
                bhi[nt][0] = p0; bhi[nt][1] = p1;
                blo[nt][0] = bf16x2_of(e0, e1);
                blo[nt][1] = bf16x2_of(e2, e3);
            }
#pragma unroll
            for (int mt = 0; mt < 2; ++mt)
#pragma unroll
                for (int nt = 0; nt < 2; ++nt) {
                    MMA_BF16(d[mt][nt], ahi[mt], bhi[nt]);
                    MMA_BF16(d[mt][nt], ahi[mt], blo[nt]);
                    MMA_BF16(d[mt][nt], alo[mt], bhi[nt]);
                }
        }

#pragma unroll
        for (int mt = 0; mt < 2; ++mt)
#pragma unroll
            for (int nt = 0; nt < 2; ++nt) {
                const int c0 = mt * 16 + ln4;
                const int b  = nt * 8 + lm4 * 2;
                *(float2*)&part[(wid * 32 + c0) * 20 + b] =
                    make_float2(d[mt][nt][0], d[mt][nt][1]);
                *(float2*)&part[(wid * 32 + c0 + 8) * 20 + b] =
                    make_float2(d[mt][nt][2], d[mt][nt][3]);
            }
        __syncthreads();

        {
            const int ri = tid >> 3;
            const int bp = tid & 7;
            u64 s = *(const u64*)&part[(ri) * 20 + 2 * bp];
#pragma unroll
            for (int w = 1; w < 8; ++w)
                s = fadd2(s, *(const u64*)&part[(w * 32 + ri) * 20 + 2 * bp]);
            float lo, hi;
            unpack2(s, lo, hi);
            gsm[(2 * bp) * 36 + ri]     = lo;
            gsm[(2 * bp + 1) * 36 + ri] = hi;
        }
        __syncthreads();

        if (tid < 128) {
            float4 gd = *(const float4*)&gsm[pb * 36 + phl * 4];
            float zf = gg.x + gd.x;
            float zi = gg.y + gd.y;
            float zo = gg.z + gd.z;
            float zc = gg.w + gd.w;
            float ft = sigmoid_ap(zf);
            float it = sigmoid_ap(zi);
            float ot = sigmoid_ap(zo);
            cstate = it * tanh_ap(zc) + ft * cstate;
            float h = ot * tanh_ap(cstate);
            __stcg(&g_h[(t + 1) & 1][(hh0 + phl) * 16 + pb], h);
            __stcs(&out[((size_t)(t * B_ + pb) << 10) + hh0 + phl], h);
            if (t + 1 < T_) {
                const float* np = Gbase + (size_t)(t + 1) * B_ * R_;
                asm volatile("prefetch.global.L2 [%0];" :: "l"(np));
            }
        }

        gsync(base + 2 + t);
    }
}

// =====================================================================
// launch
// =====================================================================
extern "C" void kernel_launch(void* const* d_in, const int* in_sizes, int n_in,
                              void* d_out, int out_size)
{
    const float* x     = (const float*)d_in[0];
    const float* wfx_w = (const float*)d_in[1];
    const float* wfx_b = (const float*)d_in[2];
    const float* wix_w = (const float*)d_in[3];
    const float* wix_b = (const float*)d_in[4];
    const float* wox_w = (const float*)d_in[5];
    const float* wox_b = (const float*)d_in[6];
    const float* wcx_w = (const float*)d_in[7];
    const float* wcx_b = (const float*)d_in[8];
    const float* tfy_w = (const float*)d_in[9];
    const float* tiy_w = (const float*)d_in[10];
    const float* toy_w = (const float*)d_in[11];
    const float* tcy_w = (const float*)d_in[12];
    const float* wym_w = (const float*)d_in[13];
    float* out = (float*)d_out;

    // dummy first: shifts ncu's captured launch (-s 5) onto lstm_rec
    dummy_k<<<1, 32>>>();

    // G = x @ Wx^T + b via split-bf16 tensor cores (ldmatrix frag path)
    gemm_input_tc<<<dim3(R_ / 64, 16000 / 128), 256>>>(
        x, wfx_w, wix_w, wox_w, wcx_w, wfx_b, wix_b, wox_b, wcx_b);

    // M fragments for the recurrence
    gemm_comb<<<dim3(R_ / 128, H_ / 128), 256>>>(
        wym_w, tfy_w, tiy_w, toy_w, tcy_w);

    cudaFuncSetAttribute(lstm_rec, cudaFuncAttributeMaxDynamicSharedMemorySize, SM_TOT);
    lstm_rec<<<NBLK, 256, SM_TOT>>>(out);
}